// round 6
// baseline (speedup 1.0000x reference)
#include <cuda_runtime.h>
#include <cuda_fp16.h>
#include <cstdint>
#include <math.h>

#define B_SZ   1024
#define RANK   256
#define NENT   100000
#define MAXNB  50

// GEMM tiling (fp16 mma.sync m16n8k16, ldmatrix feed, 2 CTA/SM)
#define BM 128
#define BN 128
#define BK 32
#define KP 40                        // padded K stride in halves (80B rows)
#define NST 4
#define A_HALVES (BM * KP)           // 5120
#define B_HALVES (BN * KP)           // 5120
#define STG_BYTES ((A_HALVES + B_HALVES) * 2)   // 20480
#define SMEM_BYTES (NST * STG_BYTES)            // 81920

#define QSCALE 524288.0f              // 2^19
#define RSCALE 512.0f                 // 2^9
#define OSCALE 3.725290298461914e-09f // 2^-28

// scratch (allocation-free rule: device globals)
__device__ __align__(16) __half g_q16[B_SZ * RANK];
__device__ __align__(16) __half g_rhs16[(size_t)NENT * RANK];
__device__ __align__(16) float g_Wt[512 * 256];
__device__ __align__(16) float g_W2t[256 * 256];

__device__ __forceinline__ void mma_f16(float* c, const uint32_t* a, uint32_t b0, uint32_t b1) {
    asm volatile(
        "mma.sync.aligned.m16n8k16.row.col.f32.f16.f16.f32 "
        "{%0,%1,%2,%3}, {%4,%5,%6,%7}, {%8,%9}, {%0,%1,%2,%3};\n"
        : "+f"(c[0]), "+f"(c[1]), "+f"(c[2]), "+f"(c[3])
        : "r"(a[0]), "r"(a[1]), "r"(a[2]), "r"(a[3]), "r"(b0), "r"(b1));
}
__device__ __forceinline__ void ldsm_x4(uint32_t* r, uint32_t addr) {
    asm volatile("ldmatrix.sync.aligned.m8n8.x4.shared.b16 {%0,%1,%2,%3}, [%4];"
                 : "=r"(r[0]), "=r"(r[1]), "=r"(r[2]), "=r"(r[3]) : "r"(addr));
}
__device__ __forceinline__ void cp16(uint32_t saddr, const void* gptr, int sz) {
    asm volatile("cp.async.cg.shared.global [%0], [%1], 16, %2;\n"
                 :: "r"(saddr), "l"(gptr), "r"(sz));
}
#define CP_COMMIT() asm volatile("cp.async.commit_group;\n" ::: "memory")
#define CP_WAIT(n)  asm volatile("cp.async.wait_group %0;\n" :: "n"(n) : "memory")

// ---------------------------------------------------------------------------
// Kernel 0: fused transpose (W_w, W2_w) + rhs_w -> fp16 convert
// ---------------------------------------------------------------------------
#define TR_BLOCKS 768
__global__ __launch_bounds__(256) void setup_kernel(const float* __restrict__ W_w,
                                                    const float* __restrict__ W2_w,
                                                    const float* __restrict__ rhs_w) {
    if (blockIdx.x < TR_BLOCKS) {
        int idx = blockIdx.x * 256 + threadIdx.x;
        if (idx < 512 * 256) {
            int i = idx >> 8, j = idx & 255;
            g_Wt[idx] = W_w[j * 512 + i];
        } else {
            int idx2 = idx - 512 * 256;
            if (idx2 < 256 * 256) {
                int k = idx2 >> 8, j = idx2 & 255;
                g_W2t[idx2] = W2_w[j * 256 + k];
            }
        }
        return;
    }
    size_t i8 = ((size_t)(blockIdx.x - TR_BLOCKS) * 256 + threadIdx.x) * 8;
    if (i8 >= (size_t)NENT * RANK) return;
    float4 v0 = *reinterpret_cast<const float4*>(rhs_w + i8);
    float4 v1 = *reinterpret_cast<const float4*>(rhs_w + i8 + 4);
    __half2 h[4];
    h[0] = __floats2half2_rn(v0.x * RSCALE, v0.y * RSCALE);
    h[1] = __floats2half2_rn(v0.z * RSCALE, v0.w * RSCALE);
    h[2] = __floats2half2_rn(v1.x * RSCALE, v1.y * RSCALE);
    h[3] = __floats2half2_rn(v1.z * RSCALE, v1.w * RSCALE);
    *reinterpret_cast<uint4*>(g_rhs16 + i8) = *reinterpret_cast<uint4*>(h);
}

// ---------------------------------------------------------------------------
// Kernel 1: prep — gathers, attention, gating (q -> scaled fp16)
// ---------------------------------------------------------------------------
__global__ __launch_bounds__(256) void prep_kernel(
    const int* __restrict__ x, const int* __restrict__ nb_idx,
    const float* __restrict__ lhs_w, const float* __restrict__ rel_w,
    const float* __restrict__ rhs_w,
    const float* __restrict__ W_b, const float* __restrict__ W2_b,
    const float* __restrict__ Wo_w, const float* __restrict__ Wo_b,
    const float* __restrict__ Uo_w, const float* __restrict__ Uo_b,
    float* __restrict__ aux)
{
    __shared__ float trp[8][512];
    __shared__ float w_sm[8][256];
    __shared__ float alpha[8][64];
    __shared__ float ctx_sm[8][256];
    __shared__ float red[8][8];
    __shared__ float g_sm[8];

    const int t = threadIdx.x;
    const int b0 = blockIdx.x * 8;
    const int lane = t & 31;
    const int warp = t >> 5;

    float lhsrel[8];
#pragma unroll
    for (int bb = 0; bb < 8; bb++) {
        int b = b0 + bb;
        int i0 = x[b * 3 + 0];
        int i1 = x[b * 3 + 1];
        int i2 = x[b * 3 + 2];
        float lv = lhs_w[(size_t)i0 * RANK + t];
        float rv = rel_w[(size_t)i1 * RANK + t];
        float hv = rhs_w[(size_t)i2 * RANK + t];
        trp[bb][t]       = lv;
        trp[bb][256 + t] = rv;
        lhsrel[bb] = lv * rv;
        if (aux) {
            aux[(size_t)b * RANK + t]              = lv;
            aux[262144 + (size_t)b * RANK + t]     = rv;
            aux[2 * 262144 + (size_t)b * RANK + t] = hv;
        }
    }
    __syncthreads();

    {
        float acc[8];
#pragma unroll
        for (int bb = 0; bb < 8; bb++) acc[bb] = 0.f;
        for (int i = 0; i < 512; i += 4) {
            float wv0 = g_Wt[(i + 0) * 256 + t];
            float wv1 = g_Wt[(i + 1) * 256 + t];
            float wv2 = g_Wt[(i + 2) * 256 + t];
            float wv3 = g_Wt[(i + 3) * 256 + t];
#pragma unroll
            for (int bb = 0; bb < 8; bb++) {
                const float4 tv = *reinterpret_cast<const float4*>(&trp[bb][i]);
                acc[bb] += wv0 * tv.x + wv1 * tv.y + wv2 * tv.z + wv3 * tv.w;
            }
        }
        float bias = W_b[t];
#pragma unroll
        for (int bb = 0; bb < 8; bb++) w_sm[bb][t] = acc[bb] + bias;
    }
    __syncthreads();

    {
        int bb = warp;
        int b = b0 + bb;
        for (int m = 0; m < MAXNB; m++) {
            int nb = __ldg(&nb_idx[b * MAXNB + m]);
            const float* r = rhs_w + (size_t)nb * RANK;
            float s = 0.f;
#pragma unroll
            for (int j = 0; j < 8; j++) {
                int k = lane + 32 * j;
                s += w_sm[bb][k] * __ldg(&r[k]);
            }
#pragma unroll
            for (int o = 16; o > 0; o >>= 1) s += __shfl_xor_sync(0xffffffffu, s, o);
            if (lane == 0) alpha[bb][m] = s;
        }
        __syncwarp();
        float v1 = (lane < MAXNB) ? alpha[bb][lane] : -1e30f;
        float v2 = (lane + 32 < MAXNB) ? alpha[bb][lane + 32] : -1e30f;
        float mx = fmaxf(v1, v2);
#pragma unroll
        for (int o = 16; o > 0; o >>= 1) mx = fmaxf(mx, __shfl_xor_sync(0xffffffffu, mx, o));
        float e1 = (lane < MAXNB) ? expf(v1 - mx) : 0.f;
        float e2 = (lane + 32 < MAXNB) ? expf(v2 - mx) : 0.f;
        float sm = e1 + e2;
#pragma unroll
        for (int o = 16; o > 0; o >>= 1) sm += __shfl_xor_sync(0xffffffffu, sm, o);
        float inv = 1.f / sm;
        if (lane < MAXNB) alpha[bb][lane] = e1 * inv;
        if (lane + 32 < MAXNB) alpha[bb][lane + 32] = e2 * inv;
    }
    __syncthreads();

#pragma unroll
    for (int bb = 0; bb < 8; bb++) {
        int base = (b0 + bb) * MAXNB;
        float acc = 0.f;
        for (int m = 0; m < MAXNB; m++) {
            int nb = __ldg(&nb_idx[base + m]);
            acc += alpha[bb][m] * __ldg(&rhs_w[(size_t)nb * RANK + t]);
        }
        ctx_sm[bb][t] = acc;
    }
    __syncthreads();

    float ec[8];
    {
        float acc[8];
#pragma unroll
        for (int bb = 0; bb < 8; bb++) acc[bb] = 0.f;
        for (int k = 0; k < 256; k += 4) {
            float w0 = g_W2t[(k + 0) * 256 + t];
            float w1 = g_W2t[(k + 1) * 256 + t];
            float w2 = g_W2t[(k + 2) * 256 + t];
            float w3 = g_W2t[(k + 3) * 256 + t];
#pragma unroll
            for (int bb = 0; bb < 8; bb++) {
                const float4 cv = *reinterpret_cast<const float4*>(&ctx_sm[bb][k]);
                acc[bb] += w0 * cv.x + w1 * cv.y + w2 * cv.z + w3 * cv.w;
            }
        }
        float bias = W2_b[t];
#pragma unroll
        for (int bb = 0; bb < 8; bb++) {
            ec[bb] = acc[bb] + bias;
            if (aux) aux[3 * 262144 + (size_t)(b0 + bb) * RANK + t] = ec[bb];
        }
    }

    {
        float uo = Uo_w[t], wo = Wo_w[t];
#pragma unroll
        for (int bb = 0; bb < 8; bb++) {
            float c = uo * lhsrel[bb] + wo * ec[bb];
#pragma unroll
            for (int o = 16; o > 0; o >>= 1) c += __shfl_xor_sync(0xffffffffu, c, o);
            if (lane == 0) red[bb][warp] = c;
        }
        __syncthreads();
        if (t < 8) {
            float s = 0.f;
#pragma unroll
            for (int w = 0; w < 8; w++) s += red[t][w];
            s += Uo_b[0] + Wo_b[0];
            g_sm[t] = 1.f / (1.f + expf(-s));
        }
        __syncthreads();
    }

#pragma unroll
    for (int bb = 0; bb < 8; bb++) {
        float g = g_sm[bb];
        float q = lhsrel[bb] * (g * ec[bb] + 1.f - g);
        g_q16[(size_t)(b0 + bb) * RANK + t] = __float2half_rn(q * QSCALE);
    }
}

// ---------------------------------------------------------------------------
// Kernel 2: fp16 GEMM, 128x128 tile, 256 threads (8 warps: 2m x 4n),
// warp tile 64x32, ldmatrix feed, 4-stage cp.async, 2 CTAs/SM.
// ---------------------------------------------------------------------------
__global__ __launch_bounds__(256, 2) void gemm_f16_kernel(float* __restrict__ out)
{
    extern __shared__ __half smem[];

    const int tid = threadIdx.x;
    const int m0 = blockIdx.x * BM;
    const int n0 = blockIdx.y * BN;
    const int lane = tid & 31;
    const int warp = tid >> 5;
    const int wm = warp & 1;     // m offset 64*wm
    const int wn = warp >> 1;    // n offset 32*wn
    const int gid = lane >> 2;
    const int qid = lane & 3;

    const uint32_t smem_u32 = (uint32_t)__cvta_generic_to_shared(smem);
    const int lrow = lane & 15;
    const int lcol16 = (lane >> 4) * 16;

    auto issue_stage = [&](int buf, int kc) {
        uint32_t base = smem_u32 + (uint32_t)buf * STG_BYTES;
#pragma unroll
        for (int i = 0; i < 2; i++) {       // A: 128 rows x 32 halves
            int idx = tid + i * 256;
            int row = idx >> 2, kq = idx & 3;
            cp16(base + (uint32_t)(row * (KP * 2) + kq * 16),
                 g_q16 + (size_t)(m0 + row) * RANK + kc + kq * 8, 16);
        }
        uint32_t bbase = base + (uint32_t)(A_HALVES * 2);
#pragma unroll
        for (int i = 0; i < 2; i++) {       // B: 128 rows x 32 halves
            int idx = tid + i * 256;
            int row = idx >> 2, kq = idx & 3;
            int nr = n0 + row;
            int ok = nr < NENT;
            cp16(bbase + (uint32_t)(row * (KP * 2) + kq * 16),
                 g_rhs16 + (size_t)(ok ? nr : 0) * RANK + kc + kq * 8, ok ? 16 : 0);
        }
    };

    float acc[4][4][4];
#pragma unroll
    for (int i = 0; i < 4; i++)
#pragma unroll
        for (int f = 0; f < 4; f++)
#pragma unroll
            for (int r = 0; r < 4; r++) acc[i][f][r] = 0.f;

    issue_stage(0, 0);      CP_COMMIT();
    issue_stage(1, BK);     CP_COMMIT();
    issue_stage(2, 2 * BK); CP_COMMIT();

#pragma unroll 1
    for (int c = 0; c < RANK / BK; c++) {
        CP_WAIT(2);
        __syncthreads();

        if (c + 3 < RANK / BK) issue_stage((c + 3) & (NST - 1), (c + 3) * BK);
        CP_COMMIT();

        const uint32_t abase = smem_u32 + (uint32_t)(c & (NST - 1)) * STG_BYTES;
        const uint32_t bbase = abase + (uint32_t)(A_HALVES * 2);

#pragma unroll
        for (int kk = 0; kk < 2; kk++) {                 // two k16 steps
            uint32_t a[4][4];
#pragma unroll
            for (int i = 0; i < 4; i++)
                ldsm_x4(a[i], abase + (uint32_t)((wm * 64 + i * 16 + lrow) * (KP * 2)
                                                 + kk * 32 + lcol16));
            uint32_t b[2][4];
#pragma unroll
            for (int j = 0; j < 2; j++)
                ldsm_x4(b[j], bbase + (uint32_t)((wn * 32 + j * 16 + lrow) * (KP * 2)
                                                 + kk * 32 + lcol16));
#pragma unroll
            for (int i = 0; i < 4; i++)
#pragma unroll
                for (int f = 0; f < 4; f++) {
                    int j = f >> 1, h = f & 1;
                    mma_f16(acc[i][f], a[i], b[j][h], b[j][h + 2]);
                }
        }
    }

    // epilogue: descale + streaming stores
#pragma unroll
    for (int i = 0; i < 4; i++) {
        int r = m0 + wm * 64 + i * 16 + gid;
#pragma unroll
        for (int f = 0; f < 4; f++) {
            int cb = n0 + wn * 32 + f * 8 + 2 * qid;
            if (cb < NENT) {
                __stcs(reinterpret_cast<float2*>(out + (size_t)r * NENT + cb),
                       make_float2(acc[i][f][0] * OSCALE, acc[i][f][1] * OSCALE));
                __stcs(reinterpret_cast<float2*>(out + (size_t)(r + 8) * NENT + cb),
                       make_float2(acc[i][f][2] * OSCALE, acc[i][f][3] * OSCALE));
            }
        }
    }
}

// ---------------------------------------------------------------------------
extern "C" void kernel_launch(void* const* d_in, const int* in_sizes, int n_in,
                              void* d_out, int out_size) {
    const int*   x      = (const int*)d_in[0];
    const int*   nb     = (const int*)d_in[1];
    const float* lhs_w  = (const float*)d_in[2];
    const float* rel_w  = (const float*)d_in[3];
    const float* rhs_w  = (const float*)d_in[4];
    const float* W_w    = (const float*)d_in[5];
    const float* W_b    = (const float*)d_in[6];
    const float* W2_w   = (const float*)d_in[7];
    const float* W2_b   = (const float*)d_in[8];
    const float* Wo_w   = (const float*)d_in[9];
    const float* Wo_b   = (const float*)d_in[10];
    const float* Uo_w   = (const float*)d_in[11];
    const float* Uo_b   = (const float*)d_in[12];
    float* out = (float*)d_out;

    float* aux = nullptr;
    if (out_size >= 102400000 + 4 * 262144) aux = out + 102400000;

    static bool attr_set = false;
    if (!attr_set) {
        cudaFuncSetAttribute(gemm_f16_kernel,
                             cudaFuncAttributeMaxDynamicSharedMemorySize, SMEM_BYTES);
        attr_set = true;
    }

    int conv_blocks = (NENT * RANK / 8 + 255) / 256;
    setup_kernel<<<TR_BLOCKS + conv_blocks, 256>>>(W_w, W2_w, rhs_w);
    prep_kernel<<<B_SZ / 8, 256>>>(x, nb, lhs_w, rel_w, rhs_w,
                                   W_b, W2_b, Wo_w, Wo_b, Uo_w, Uo_b, aux);
    dim3 grid(B_SZ / BM, (NENT + BN - 1) / BN);
    gemm_f16_kernel<<<grid, 256, SMEM_BYTES>>>(out);
}

// round 7
// speedup vs baseline: 1.5123x; 1.5123x over previous
#include <cuda_runtime.h>
#include <cuda_fp16.h>
#include <cstdint>
#include <math.h>

#define B_SZ   1024
#define RANK   256
#define NENT   100000
#define MAXNB  50

// GEMM tiling (fp16 mma.sync m16n8k16, ldmatrix feed)
#define BM 128
#define BN 256
#define BK 64
#define KP 72                        // padded K stride in halves (144B rows)
#define NST 3
#define NCHUNK (RANK / BK)           // 4
#define A_HALVES (BM * KP)           // 9216
#define B_HALVES (BN * KP)           // 18432
#define STG_BYTES ((A_HALVES + B_HALVES) * 2)   // 55296
#define SMEM_BYTES (NST * STG_BYTES)            // 165888

#define QSCALE 524288.0f              // 2^19
#define RSCALE 512.0f                 // 2^9
#define OSCALE 3.725290298461914e-09f // 2^-28

// scratch (allocation-free rule: device globals)
__device__ __align__(16) __half g_q16[B_SZ * RANK];
__device__ __align__(16) __half g_rhs16[(size_t)NENT * RANK];
__device__ __align__(16) float g_Wt[512 * 256];
__device__ __align__(16) float g_W2t[256 * 256];

__device__ __forceinline__ void mma_f16(float* c, const uint32_t* a, uint32_t b0, uint32_t b1) {
    asm volatile(
        "mma.sync.aligned.m16n8k16.row.col.f32.f16.f16.f32 "
        "{%0,%1,%2,%3}, {%4,%5,%6,%7}, {%8,%9}, {%0,%1,%2,%3};\n"
        : "+f"(c[0]), "+f"(c[1]), "+f"(c[2]), "+f"(c[3])
        : "r"(a[0]), "r"(a[1]), "r"(a[2]), "r"(a[3]), "r"(b0), "r"(b1));
}
__device__ __forceinline__ void ldsm_x4(uint32_t* r, uint32_t addr) {
    asm volatile("ldmatrix.sync.aligned.m8n8.x4.shared.b16 {%0,%1,%2,%3}, [%4];"
                 : "=r"(r[0]), "=r"(r[1]), "=r"(r[2]), "=r"(r[3]) : "r"(addr));
}
__device__ __forceinline__ void cp16(uint32_t saddr, const void* gptr, int sz) {
    asm volatile("cp.async.cg.shared.global [%0], [%1], 16, %2;\n"
                 :: "r"(saddr), "l"(gptr), "r"(sz));
}
#define CP_COMMIT() asm volatile("cp.async.commit_group;\n" ::: "memory")
#define CP_WAIT(n)  asm volatile("cp.async.wait_group %0;\n" :: "n"(n) : "memory")

// ---------------------------------------------------------------------------
// Kernel 0: fused transpose (W_w, W2_w) + rhs_w -> fp16 convert
// ---------------------------------------------------------------------------
#define TR_BLOCKS 768
__global__ __launch_bounds__(256) void setup_kernel(const float* __restrict__ W_w,
                                                    const float* __restrict__ W2_w,
                                                    const float* __restrict__ rhs_w) {
    if (blockIdx.x < TR_BLOCKS) {
        int idx = blockIdx.x * 256 + threadIdx.x;
        if (idx < 512 * 256) {
            int i = idx >> 8, j = idx & 255;
            g_Wt[idx] = W_w[j * 512 + i];
        } else {
            int idx2 = idx - 512 * 256;
            if (idx2 < 256 * 256) {
                int k = idx2 >> 8, j = idx2 & 255;
                g_W2t[idx2] = W2_w[j * 256 + k];
            }
        }
        return;
    }
    size_t i8 = ((size_t)(blockIdx.x - TR_BLOCKS) * 256 + threadIdx.x) * 8;
    if (i8 >= (size_t)NENT * RANK) return;
    float4 v0 = *reinterpret_cast<const float4*>(rhs_w + i8);
    float4 v1 = *reinterpret_cast<const float4*>(rhs_w + i8 + 4);
    __half2 h[4];
    h[0] = __floats2half2_rn(v0.x * RSCALE, v0.y * RSCALE);
    h[1] = __floats2half2_rn(v0.z * RSCALE, v0.w * RSCALE);
    h[2] = __floats2half2_rn(v1.x * RSCALE, v1.y * RSCALE);
    h[3] = __floats2half2_rn(v1.z * RSCALE, v1.w * RSCALE);
    *reinterpret_cast<uint4*>(g_rhs16 + i8) = *reinterpret_cast<uint4*>(h);
}

// ---------------------------------------------------------------------------
// Kernel 1: prep — gathers, single-pass online-softmax attention, gating
// ---------------------------------------------------------------------------
__global__ __launch_bounds__(256) void prep_kernel(
    const int* __restrict__ x, const int* __restrict__ nb_idx,
    const float* __restrict__ lhs_w, const float* __restrict__ rel_w,
    const float* __restrict__ rhs_w,
    const float* __restrict__ W_b, const float* __restrict__ W2_b,
    const float* __restrict__ Wo_w, const float* __restrict__ Wo_b,
    const float* __restrict__ Uo_w, const float* __restrict__ Uo_b,
    float* __restrict__ aux)
{
    __shared__ float trp[8][512];
    __shared__ float w_sm[8][256];
    __shared__ float ctx_sm[8][256];
    __shared__ float red[8][8];
    __shared__ float g_sm[8];

    const int t = threadIdx.x;
    const int b0 = blockIdx.x * 8;
    const int lane = t & 31;
    const int warp = t >> 5;

    float lhsrel[8];
#pragma unroll
    for (int bb = 0; bb < 8; bb++) {
        int b = b0 + bb;
        int i0 = x[b * 3 + 0];
        int i1 = x[b * 3 + 1];
        int i2 = x[b * 3 + 2];
        float lv = lhs_w[(size_t)i0 * RANK + t];
        float rv = rel_w[(size_t)i1 * RANK + t];
        float hv = rhs_w[(size_t)i2 * RANK + t];
        trp[bb][t]       = lv;
        trp[bb][256 + t] = rv;
        lhsrel[bb] = lv * rv;
        if (aux) {
            aux[(size_t)b * RANK + t]              = lv;
            aux[262144 + (size_t)b * RANK + t]     = rv;
            aux[2 * 262144 + (size_t)b * RANK + t] = hv;
        }
    }
    __syncthreads();

    // w = trp_E @ W_w.T + W_b
    {
        float acc[8];
#pragma unroll
        for (int bb = 0; bb < 8; bb++) acc[bb] = 0.f;
        for (int i = 0; i < 512; i += 4) {
            float wv0 = g_Wt[(i + 0) * 256 + t];
            float wv1 = g_Wt[(i + 1) * 256 + t];
            float wv2 = g_Wt[(i + 2) * 256 + t];
            float wv3 = g_Wt[(i + 3) * 256 + t];
#pragma unroll
            for (int bb = 0; bb < 8; bb++) {
                const float4 tv = *reinterpret_cast<const float4*>(&trp[bb][i]);
                acc[bb] += wv0 * tv.x + wv1 * tv.y + wv2 * tv.z + wv3 * tv.w;
            }
        }
        float bias = W_b[t];
#pragma unroll
        for (int bb = 0; bb < 8; bb++) w_sm[bb][t] = acc[bb] + bias;
    }
    __syncthreads();

    // single-pass online softmax + ctx accumulation (warp per row)
    {
        int bb = warp;
        int b = b0 + bb;
        float ctx_acc[8];
#pragma unroll
        for (int j = 0; j < 8; j++) ctx_acc[j] = 0.f;
        float Mx = -1e30f, den = 0.f;
        for (int m = 0; m < MAXNB; m++) {
            int nb = __ldg(&nb_idx[b * MAXNB + m]);
            const float* r = rhs_w + (size_t)nb * RANK;
            float rv[8];
            float s = 0.f;
#pragma unroll
            for (int j = 0; j < 8; j++) {
                int k = lane + 32 * j;
                rv[j] = __ldg(&r[k]);
                s += w_sm[bb][k] * rv[j];
            }
#pragma unroll
            for (int o = 16; o > 0; o >>= 1) s += __shfl_xor_sync(0xffffffffu, s, o);
            float Mn = fmaxf(Mx, s);
            float scale = __expf(Mx - Mn);
            float p = __expf(s - Mn);
            den = den * scale + p;
#pragma unroll
            for (int j = 0; j < 8; j++) ctx_acc[j] = ctx_acc[j] * scale + p * rv[j];
            Mx = Mn;
        }
        float inv = 1.f / den;
#pragma unroll
        for (int j = 0; j < 8; j++) ctx_sm[bb][lane + 32 * j] = ctx_acc[j] * inv;
    }
    __syncthreads();

    // e_c = ctx @ W2_w.T + W2_b
    float ec[8];
    {
        float acc[8];
#pragma unroll
        for (int bb = 0; bb < 8; bb++) acc[bb] = 0.f;
        for (int k = 0; k < 256; k += 4) {
            float w0 = g_W2t[(k + 0) * 256 + t];
            float w1 = g_W2t[(k + 1) * 256 + t];
            float w2 = g_W2t[(k + 2) * 256 + t];
            float w3 = g_W2t[(k + 3) * 256 + t];
#pragma unroll
            for (int bb = 0; bb < 8; bb++) {
                const float4 cv = *reinterpret_cast<const float4*>(&ctx_sm[bb][k]);
                acc[bb] += w0 * cv.x + w1 * cv.y + w2 * cv.z + w3 * cv.w;
            }
        }
        float bias = W2_b[t];
#pragma unroll
        for (int bb = 0; bb < 8; bb++) {
            ec[bb] = acc[bb] + bias;
            if (aux) aux[3 * 262144 + (size_t)(b0 + bb) * RANK + t] = ec[bb];
        }
    }

    // gate
    {
        float uo = Uo_w[t], wo = Wo_w[t];
#pragma unroll
        for (int bb = 0; bb < 8; bb++) {
            float c = uo * lhsrel[bb] + wo * ec[bb];
#pragma unroll
            for (int o = 16; o > 0; o >>= 1) c += __shfl_xor_sync(0xffffffffu, c, o);
            if (lane == 0) red[bb][warp] = c;
        }
        __syncthreads();
        if (t < 8) {
            float s = 0.f;
#pragma unroll
            for (int w = 0; w < 8; w++) s += red[t][w];
            s += Uo_b[0] + Wo_b[0];
            g_sm[t] = 1.f / (1.f + expf(-s));
        }
        __syncthreads();
    }

#pragma unroll
    for (int bb = 0; bb < 8; bb++) {
        float g = g_sm[bb];
        float q = lhsrel[bb] * (g * ec[bb] + 1.f - g);
        g_q16[(size_t)(b0 + bb) * RANK + t] = __float2half_rn(q * QSCALE);
    }
}

// ---------------------------------------------------------------------------
// Kernel 2: fp16 GEMM, 128x256 tile, 256 threads (8 warps: 2m x 4n),
// warp tile 64x64, BK=64 chunks (4 syncs total), ldmatrix feed, 3-stage cp.async.
// ---------------------------------------------------------------------------
__global__ __launch_bounds__(256, 1) void gemm_f16_kernel(float* __restrict__ out)
{
    extern __shared__ __half smem[];

    const int tid = threadIdx.x;
    const int m0 = blockIdx.x * BM;
    const int n0 = blockIdx.y * BN;
    const int lane = tid & 31;
    const int warp = tid >> 5;
    const int wm = warp & 1;     // m offset 64*wm
    const int wn = warp >> 1;    // n offset 64*wn
    const int gid = lane >> 2;
    const int qid = lane & 3;

    const uint32_t smem_u32 = (uint32_t)__cvta_generic_to_shared(smem);
    const int lrow = lane & 15;
    const int lcol16 = (lane >> 4) * 16;

    auto issue_stage = [&](int buf, int kc) {
        uint32_t base = smem_u32 + (uint32_t)buf * STG_BYTES;
#pragma unroll
        for (int i = 0; i < 4; i++) {       // A: 128 rows x 64 halves
            int idx = tid + i * 256;
            int row = idx >> 3, kq = idx & 7;
            cp16(base + (uint32_t)(row * (KP * 2) + kq * 16),
                 g_q16 + (size_t)(m0 + row) * RANK + kc + kq * 8, 16);
        }
        uint32_t bbase = base + (uint32_t)(A_HALVES * 2);
#pragma unroll
        for (int i = 0; i < 8; i++) {       // B: 256 rows x 64 halves
            int idx = tid + i * 256;
            int row = idx >> 3, kq = idx & 7;
            int nr = n0 + row;
            int ok = nr < NENT;
            cp16(bbase + (uint32_t)(row * (KP * 2) + kq * 16),
                 g_rhs16 + (size_t)(ok ? nr : 0) * RANK + kc + kq * 8, ok ? 16 : 0);
        }
    };

    float acc[4][8][4];
#pragma unroll
    for (int i = 0; i < 4; i++)
#pragma unroll
        for (int tn = 0; tn < 8; tn++)
#pragma unroll
            for (int r = 0; r < 4; r++) acc[i][tn][r] = 0.f;

    issue_stage(0, 0);  CP_COMMIT();
    issue_stage(1, BK); CP_COMMIT();

#pragma unroll 1
    for (int c = 0; c < NCHUNK; c++) {
        CP_WAIT(1);
        __syncthreads();

        if (c + 2 < NCHUNK) issue_stage((c + 2) % NST, (c + 2) * BK);
        CP_COMMIT();

        const uint32_t abase = smem_u32 + (uint32_t)(c % NST) * STG_BYTES;
        const uint32_t bbase = abase + (uint32_t)(A_HALVES * 2);

#pragma unroll
        for (int kk = 0; kk < BK / 16; kk++) {           // four k16 steps
            uint32_t a[4][4];
#pragma unroll
            for (int i = 0; i < 4; i++)
                ldsm_x4(a[i], abase + (uint32_t)((wm * 64 + i * 16 + lrow) * (KP * 2)
                                                 + kk * 32 + lcol16));
            uint32_t b[4][4];
#pragma unroll
            for (int j = 0; j < 4; j++)
                ldsm_x4(b[j], bbase + (uint32_t)((wn * 64 + j * 16 + lrow) * (KP * 2)
                                                 + kk * 32 + lcol16));
#pragma unroll
            for (int i = 0; i < 4; i++)
#pragma unroll
                for (int tn = 0; tn < 8; tn++) {
                    int j = tn >> 1, h = tn & 1;
                    mma_f16(acc[i][tn], a[i], b[j][h], b[j][h + 2]);
                }
        }
    }

    // epilogue: descale + streaming stores
#pragma unroll
    for (int i = 0; i < 4; i++) {
        int r = m0 + wm * 64 + i * 16 + gid;
#pragma unroll
        for (int tn = 0; tn < 8; tn++) {
            int cb = n0 + wn * 64 + tn * 8 + 2 * qid;
            if (cb < NENT) {
                __stcs(reinterpret_cast<float2*>(out + (size_t)r * NENT + cb),
                       make_float2(acc[i][tn][0] * OSCALE, acc[i][tn][1] * OSCALE));
                __stcs(reinterpret_cast<float2*>(out + (size_t)(r + 8) * NENT + cb),
                       make_float2(acc[i][tn][2] * OSCALE, acc[i][tn][3] * OSCALE));
            }
        }
    }
}

// ---------------------------------------------------------------------------
extern "C" void kernel_launch(void* const* d_in, const int* in_sizes, int n_in,
                              void* d_out, int out_size) {
    const int*   x      = (const int*)d_in[0];
    const int*   nb     = (const int*)d_in[1];
    const float* lhs_w  = (const float*)d_in[2];
    const float* rel_w  = (const float*)d_in[3];
    const float* rhs_w  = (const float*)d_in[4];
    const float* W_w    = (const float*)d_in[5];
    const float* W_b    = (const float*)d_in[6];
    const float* W2_w   = (const float*)d_in[7];
    const float* W2_b   = (const float*)d_in[8];
    const float* Wo_w   = (const float*)d_in[9];
    const float* Wo_b   = (const float*)d_in[10];
    const float* Uo_w   = (const float*)d_in[11];
    const float* Uo_b   = (const float*)d_in[12];
    float* out = (float*)d_out;

    float* aux = nullptr;
    if (out_size >= 102400000 + 4 * 262144) aux = out + 102400000;

    static bool attr_set = false;
    if (!attr_set) {
        cudaFuncSetAttribute(gemm_f16_kernel,
                             cudaFuncAttributeMaxDynamicSharedMemorySize, SMEM_BYTES);
        attr_set = true;
    }

    int conv_blocks = (NENT * RANK / 8 + 255) / 256;
    setup_kernel<<<TR_BLOCKS + conv_blocks, 256>>>(W_w, W2_w, rhs_w);
    prep_kernel<<<B_SZ / 8, 256>>>(x, nb, lhs_w, rel_w, rhs_w,
                                   W_b, W2_b, Wo_w, Wo_b, Uo_w, Uo_b, aux);
    dim3 grid(B_SZ / BM, (NENT + BN - 1) / BN);
    gemm_f16_kernel<<<grid, 256, SMEM_BYTES>>>(out);
}

// round 8
// speedup vs baseline: 1.5311x; 1.0124x over previous
#include <cuda_runtime.h>
#include <cuda_fp16.h>
#include <cstdint>
#include <math.h>

#define B_SZ   1024
#define RANK   256
#define NENT   100000
#define MAXNB  50

// GEMM tiling: 128x256 tile, K split into 2 chunks of 128 halves (256B/row),
// both chunks resident in smem (no ring), cp.async.bulk + mbarrier feed.
#define BM 128
#define BN 256
#define BKC 128                       // halves per chunk
#define KP 136                        // pitch in halves (272B; 272%128=16 -> LDSM conflict-free)
#define ROW_BYTES 256                 // bytes copied per row per chunk
#define A_STG (BM * KP * 2)           // 34816 B
#define B_STG (BN * KP * 2)           // 69632 B
#define STG_BYTES (A_STG + B_STG)     // 104448 B
#define SM_CTRL 128
#define SMEM_BYTES (SM_CTRL + 2 * STG_BYTES)   // 209024 B

#define QSCALE 524288.0f              // 2^19
#define RSCALE 512.0f                 // 2^9
#define OSCALE 3.725290298461914e-09f // 2^-28

// scratch (allocation-free rule: device globals)
__device__ __align__(16) __half g_q16[B_SZ * RANK];
__device__ __align__(16) __half g_rhs16[(size_t)NENT * RANK];
__device__ __align__(16) float g_Wt[512 * 256];
__device__ __align__(16) float g_W2t[256 * 256];

__device__ __forceinline__ void mma_f16(float* c, const uint32_t* a, uint32_t b0, uint32_t b1) {
    asm volatile(
        "mma.sync.aligned.m16n8k16.row.col.f32.f16.f16.f32 "
        "{%0,%1,%2,%3}, {%4,%5,%6,%7}, {%8,%9}, {%0,%1,%2,%3};\n"
        : "+f"(c[0]), "+f"(c[1]), "+f"(c[2]), "+f"(c[3])
        : "r"(a[0]), "r"(a[1]), "r"(a[2]), "r"(a[3]), "r"(b0), "r"(b1));
}
__device__ __forceinline__ void ldsm_x4(uint32_t* r, uint32_t addr) {
    asm volatile("ldmatrix.sync.aligned.m8n8.x4.shared.b16 {%0,%1,%2,%3}, [%4];"
                 : "=r"(r[0]), "=r"(r[1]), "=r"(r[2]), "=r"(r[3]) : "r"(addr));
}
__device__ __forceinline__ void bulk_cp(uint32_t dst, const void* src, uint32_t bytes,
                                        uint32_t mbar) {
    asm volatile(
        "cp.async.bulk.shared::cluster.global.mbarrier::complete_tx::bytes "
        "[%0], [%1], %2, [%3];"
        :: "r"(dst), "l"(src), "r"(bytes), "r"(mbar) : "memory");
}
#define MBARRIER_INIT(a, cnt) \
    asm volatile("mbarrier.init.shared.b64 [%0], %1;" \
                 :: "r"((uint32_t)(a)), "r"((uint32_t)(cnt)) : "memory")
#define MBARRIER_EXPECT_TX(a, bytes) \
    asm volatile("mbarrier.arrive.expect_tx.shared.b64 _, [%0], %1;" \
                 :: "r"((uint32_t)(a)), "r"((uint32_t)(bytes)) : "memory")
#define MBARRIER_WAIT_PARITY(a, par) do {                                        \
    uint32_t _m = (uint32_t)(a), _p = (uint32_t)(par), _d;                       \
    asm volatile("{\n\t.reg .pred p;\n\t"                                        \
        "mbarrier.try_wait.parity.acquire.cta.shared::cta.b64 p, [%1], %2;\n\t"  \
        "selp.b32 %0, 1, 0, p;\n\t}" : "=r"(_d) : "r"(_m), "r"(_p) : "memory");  \
    if (!_d) {                                                                   \
        asm volatile("{\n\t.reg .pred P1;\n\t"                                   \
            "WL_%=:\n\t"                                                         \
            "mbarrier.try_wait.parity.acquire.cta.shared::cta.b64 P1, [%0], %1, 0x989680;\n\t" \
            "@P1 bra.uni WD_%=;\n\tbra.uni WL_%=;\n\tWD_%=:\n\t}"                \
            :: "r"(_m), "r"(_p) : "memory");                                     \
    }                                                                            \
} while (0)

// ---------------------------------------------------------------------------
// Kernel 0: fused transpose (W_w, W2_w) + rhs_w -> fp16 convert
// ---------------------------------------------------------------------------
#define TR_BLOCKS 768
__global__ __launch_bounds__(256) void setup_kernel(const float* __restrict__ W_w,
                                                    const float* __restrict__ W2_w,
                                                    const float* __restrict__ rhs_w) {
    if (blockIdx.x < TR_BLOCKS) {
        int idx = blockIdx.x * 256 + threadIdx.x;
        if (idx < 512 * 256) {
            int i = idx >> 8, j = idx & 255;
            g_Wt[idx] = W_w[j * 512 + i];
        } else {
            int idx2 = idx - 512 * 256;
            if (idx2 < 256 * 256) {
                int k = idx2 >> 8, j = idx2 & 255;
                g_W2t[idx2] = W2_w[j * 256 + k];
            }
        }
        return;
    }
    size_t i8 = ((size_t)(blockIdx.x - TR_BLOCKS) * 256 + threadIdx.x) * 8;
    if (i8 >= (size_t)NENT * RANK) return;
    float4 v0 = *reinterpret_cast<const float4*>(rhs_w + i8);
    float4 v1 = *reinterpret_cast<const float4*>(rhs_w + i8 + 4);
    __half2 h[4];
    h[0] = __floats2half2_rn(v0.x * RSCALE, v0.y * RSCALE);
    h[1] = __floats2half2_rn(v0.z * RSCALE, v0.w * RSCALE);
    h[2] = __floats2half2_rn(v1.x * RSCALE, v1.y * RSCALE);
    h[3] = __floats2half2_rn(v1.z * RSCALE, v1.w * RSCALE);
    *reinterpret_cast<uint4*>(g_rhs16 + i8) = *reinterpret_cast<uint4*>(h);
}

// ---------------------------------------------------------------------------
// Kernel 1: prep — gathers, single-pass online-softmax attention, gating
// ---------------------------------------------------------------------------
__global__ __launch_bounds__(256) void prep_kernel(
    const int* __restrict__ x, const int* __restrict__ nb_idx,
    const float* __restrict__ lhs_w, const float* __restrict__ rel_w,
    const float* __restrict__ rhs_w,
    const float* __restrict__ W_b, const float* __restrict__ W2_b,
    const float* __restrict__ Wo_w, const float* __restrict__ Wo_b,
    const float* __restrict__ Uo_w, const float* __restrict__ Uo_b,
    float* __restrict__ aux)
{
    __shared__ float trp[8][512];
    __shared__ float w_sm[8][256];
    __shared__ float ctx_sm[8][256];
    __shared__ float red[8][8];
    __shared__ float g_sm[8];

    const int t = threadIdx.x;
    const int b0 = blockIdx.x * 8;
    const int lane = t & 31;
    const int warp = t >> 5;

    float lhsrel[8];
#pragma unroll
    for (int bb = 0; bb < 8; bb++) {
        int b = b0 + bb;
        int i0 = x[b * 3 + 0];
        int i1 = x[b * 3 + 1];
        int i2 = x[b * 3 + 2];
        float lv = lhs_w[(size_t)i0 * RANK + t];
        float rv = rel_w[(size_t)i1 * RANK + t];
        float hv = rhs_w[(size_t)i2 * RANK + t];
        trp[bb][t]       = lv;
        trp[bb][256 + t] = rv;
        lhsrel[bb] = lv * rv;
        if (aux) {
            aux[(size_t)b * RANK + t]              = lv;
            aux[262144 + (size_t)b * RANK + t]     = rv;
            aux[2 * 262144 + (size_t)b * RANK + t] = hv;
        }
    }
    __syncthreads();

    // w = trp_E @ W_w.T + W_b
    {
        float acc[8];
#pragma unroll
        for (int bb = 0; bb < 8; bb++) acc[bb] = 0.f;
        for (int i = 0; i < 512; i += 4) {
            float wv0 = g_Wt[(i + 0) * 256 + t];
            float wv1 = g_Wt[(i + 1) * 256 + t];
            float wv2 = g_Wt[(i + 2) * 256 + t];
            float wv3 = g_Wt[(i + 3) * 256 + t];
#pragma unroll
            for (int bb = 0; bb < 8; bb++) {
                const float4 tv = *reinterpret_cast<const float4*>(&trp[bb][i]);
                acc[bb] += wv0 * tv.x + wv1 * tv.y + wv2 * tv.z + wv3 * tv.w;
            }
        }
        float bias = W_b[t];
#pragma unroll
        for (int bb = 0; bb < 8; bb++) w_sm[bb][t] = acc[bb] + bias;
    }
    __syncthreads();

    // single-pass online softmax + ctx accumulation (warp per row)
    {
        int bb = warp;
        int b = b0 + bb;
        float ctx_acc[8];
#pragma unroll
        for (int j = 0; j < 8; j++) ctx_acc[j] = 0.f;
        float Mx = -1e30f, den = 0.f;
        for (int m = 0; m < MAXNB; m++) {
            int nb = __ldg(&nb_idx[b * MAXNB + m]);
            const float* r = rhs_w + (size_t)nb * RANK;
            float rv[8];
            float s = 0.f;
#pragma unroll
            for (int j = 0; j < 8; j++) {
                int k = lane + 32 * j;
                rv[j] = __ldg(&r[k]);
                s += w_sm[bb][k] * rv[j];
            }
#pragma unroll
            for (int o = 16; o > 0; o >>= 1) s += __shfl_xor_sync(0xffffffffu, s, o);
            float Mn = fmaxf(Mx, s);
            float scale = __expf(Mx - Mn);
            float p = __expf(s - Mn);
            den = den * scale + p;
#pragma unroll
            for (int j = 0; j < 8; j++) ctx_acc[j] = ctx_acc[j] * scale + p * rv[j];
            Mx = Mn;
        }
        float inv = 1.f / den;
#pragma unroll
        for (int j = 0; j < 8; j++) ctx_sm[bb][lane + 32 * j] = ctx_acc[j] * inv;
    }
    __syncthreads();

    // e_c = ctx @ W2_w.T + W2_b
    float ec[8];
    {
        float acc[8];
#pragma unroll
        for (int bb = 0; bb < 8; bb++) acc[bb] = 0.f;
        for (int k = 0; k < 256; k += 4) {
            float w0 = g_W2t[(k + 0) * 256 + t];
            float w1 = g_W2t[(k + 1) * 256 + t];
            float w2 = g_W2t[(k + 2) * 256 + t];
            float w3 = g_W2t[(k + 3) * 256 + t];
#pragma unroll
            for (int bb = 0; bb < 8; bb++) {
                const float4 cv = *reinterpret_cast<const float4*>(&ctx_sm[bb][k]);
                acc[bb] += w0 * cv.x + w1 * cv.y + w2 * cv.z + w3 * cv.w;
            }
        }
        float bias = W2_b[t];
#pragma unroll
        for (int bb = 0; bb < 8; bb++) {
            ec[bb] = acc[bb] + bias;
            if (aux) aux[3 * 262144 + (size_t)(b0 + bb) * RANK + t] = ec[bb];
        }
    }

    // gate
    {
        float uo = Uo_w[t], wo = Wo_w[t];
#pragma unroll
        for (int bb = 0; bb < 8; bb++) {
            float c = uo * lhsrel[bb] + wo * ec[bb];
#pragma unroll
            for (int o = 16; o > 0; o >>= 1) c += __shfl_xor_sync(0xffffffffu, c, o);
            if (lane == 0) red[bb][warp] = c;
        }
        __syncthreads();
        if (t < 8) {
            float s = 0.f;
#pragma unroll
            for (int w = 0; w < 8; w++) s += red[t][w];
            s += Uo_b[0] + Wo_b[0];
            g_sm[t] = 1.f / (1.f + expf(-s));
        }
        __syncthreads();
    }

#pragma unroll
    for (int bb = 0; bb < 8; bb++) {
        float g = g_sm[bb];
        float q = lhsrel[bb] * (g * ec[bb] + 1.f - g);
        g_q16[(size_t)(b0 + bb) * RANK + t] = __float2half_rn(q * QSCALE);
    }
}

// ---------------------------------------------------------------------------
// Kernel 2: fp16 GEMM, 128x256 tile, 8 warps (2m x 4n, warp tile 64x64).
// Feed: cp.async.bulk (256B per row per chunk) -> 2 resident K-chunks,
// mbarrier completion; ldmatrix fragments; streaming stores.
// ---------------------------------------------------------------------------
__global__ __launch_bounds__(256, 1) void gemm_f16_kernel(float* __restrict__ out)
{
    extern __shared__ __half smem[];

    const int tid = threadIdx.x;
    const int m0 = blockIdx.x * BM;
    const int n0 = blockIdx.y * BN;
    const int lane = tid & 31;
    const int warp = tid >> 5;
    const int wm = warp & 1;     // m offset 64*wm
    const int wn = warp >> 1;    // n offset 64*wn
    const int gid = lane >> 2;
    const int qid = lane & 3;

    const uint32_t smem_u32 = (uint32_t)__cvta_generic_to_shared(smem);
    const uint32_t mbar0 = smem_u32;                 // mbar[2] at +0, +8
    const int vb = min(BN, NENT - n0);               // valid B rows in this tile

    if (tid == 0) {
        MBARRIER_INIT(mbar0 + 0, 1);
        MBARRIER_INIT(mbar0 + 8, 1);
    }
    // zero-fill invalid B rows (edge tile only) so HMMA sees finite garbage
    if (vb < BN) {
        int zrows = BN - vb;
        for (int i = tid; i < zrows * (KP / 8) * 2; i += 256) {   // uint4 per 8 halves, 2 stages
            int st = i / (zrows * (KP / 8));
            int r = (i / (KP / 8)) % zrows;
            int c = i % (KP / 8);
            uint32_t a = smem_u32 + SM_CTRL + st * STG_BYTES + A_STG
                       + (uint32_t)((vb + r) * KP * 2 + c * 16);
            asm volatile("st.shared.v4.b32 [%0], {%1,%1,%1,%1};" :: "r"(a), "r"(0) : "memory");
        }
    }
    __syncthreads();
    if (tid == 0) {
        MBARRIER_EXPECT_TX(mbar0 + 0, (uint32_t)(BM + vb) * ROW_BYTES);
        MBARRIER_EXPECT_TX(mbar0 + 8, (uint32_t)(BM + vb) * ROW_BYTES);
    }
    __syncthreads();

    // issue all loads: one 256B bulk copy per row per chunk
#pragma unroll
    for (int ch = 0; ch < 2; ch++) {
        const uint32_t sb = smem_u32 + SM_CTRL + ch * STG_BYTES;
        const uint32_t mb = mbar0 + ch * 8;
        if (tid < BM)
            bulk_cp(sb + (uint32_t)(tid * KP * 2),
                    g_q16 + (size_t)(m0 + tid) * RANK + ch * BKC, ROW_BYTES, mb);
        if (tid < vb)
            bulk_cp(sb + A_STG + (uint32_t)(tid * KP * 2),
                    g_rhs16 + (size_t)(n0 + tid) * RANK + ch * BKC, ROW_BYTES, mb);
    }

    float acc[4][8][4];
#pragma unroll
    for (int i = 0; i < 4; i++)
#pragma unroll
        for (int tn = 0; tn < 8; tn++)
#pragma unroll
            for (int r = 0; r < 4; r++) acc[i][tn][r] = 0.f;

    const int lrow = lane & 15;
    const int lcol16 = (lane >> 4) * 16;

#pragma unroll
    for (int ch = 0; ch < 2; ch++) {
        MBARRIER_WAIT_PARITY(mbar0 + ch * 8, 0);
        const uint32_t abase = smem_u32 + SM_CTRL + ch * STG_BYTES;
        const uint32_t bbase = abase + A_STG;

#pragma unroll
        for (int kk = 0; kk < BKC / 16; kk++) {          // eight k16 steps
            uint32_t a[4][4];
#pragma unroll
            for (int i = 0; i < 4; i++)
                ldsm_x4(a[i], abase + (uint32_t)((wm * 64 + i * 16 + lrow) * (KP * 2)
                                                 + kk * 32 + lcol16));
            uint32_t b[4][4];
#pragma unroll
            for (int j = 0; j < 4; j++)
                ldsm_x4(b[j], bbase + (uint32_t)((wn * 64 + j * 16 + lrow) * (KP * 2)
                                                 + kk * 32 + lcol16));
#pragma unroll
            for (int i = 0; i < 4; i++)
#pragma unroll
                for (int tn = 0; tn < 8; tn++) {
                    int j = tn >> 1, h = tn & 1;
                    mma_f16(acc[i][tn], a[i], b[j][h], b[j][h + 2]);
                }
        }
    }

    // epilogue: descale + streaming stores
#pragma unroll
    for (int i = 0; i < 4; i++) {
        int r = m0 + wm * 64 + i * 16 + gid;
#pragma unroll
        for (int tn = 0; tn < 8; tn++) {
            int cb = n0 + wn * 64 + tn * 8 + 2 * qid;
            if (cb < NENT) {
                __stcs(reinterpret_cast<float2*>(out + (size_t)r * NENT + cb),
                       make_float2(acc[i][tn][0] * OSCALE, acc[i][tn][1] * OSCALE));
                __stcs(reinterpret_cast<float2*>(out + (size_t)(r + 8) * NENT + cb),
                       make_float2(acc[i][tn][2] * OSCALE, acc[i][tn][3] * OSCALE));
            }
        }
    }
}

// ---------------------------------------------------------------------------
extern "C" void kernel_launch(void* const* d_in, const int* in_sizes, int n_in,
                              void* d_out, int out_size) {
    const int*   x      = (const int*)d_in[0];
    const int*   nb     = (const int*)d_in[1];
    const float* lhs_w  = (const float*)d_in[2];
    const float* rel_w  = (const float*)d_in[3];
    const float* rhs_w  = (const float*)d_in[4];
    const float* W_w    = (const float*)d_in[5];
    const float* W_b    = (const float*)d_in[6];
    const float* W2_w   = (const float*)d_in[7];
    const float* W2_b   = (const float*)d_in[8];
    const float* Wo_w   = (const float*)d_in[9];
    const float* Wo_b   = (const float*)d_in[10];
    const float* Uo_w   = (const float*)d_in[11];
    const float* Uo_b   = (const float*)d_in[12];
    float* out = (float*)d_out;

    float* aux = nullptr;
    if (out_size >= 102400000 + 4 * 262144) aux = out + 102400000;

    static bool attr_set = false;
    if (!attr_set) {
        cudaFuncSetAttribute(gemm_f16_kernel,
                             cudaFuncAttributeMaxDynamicSharedMemorySize, SMEM_BYTES);
        attr_set = true;
    }

    int conv_blocks = (NENT * RANK / 8 + 255) / 256;
    setup_kernel<<<TR_BLOCKS + conv_blocks, 256>>>(W_w, W2_w, rhs_w);
    prep_kernel<<<B_SZ / 8, 256>>>(x, nb, lhs_w, rel_w, rhs_w,
                                   W_b, W2_b, Wo_w, Wo_b, Uo_w, Uo_b, aux);
    dim3 grid(B_SZ / BM, (NENT + BN - 1) / BN);
    gemm_f16_kernel<<<grid, 256, SMEM_BYTES>>>(out);
}

// round 9
// speedup vs baseline: 1.6934x; 1.1060x over previous
#include <cuda_runtime.h>
#include <cuda_fp16.h>
#include <cstdint>
#include <math.h>

#define B_SZ   1024
#define RANK   256
#define NENT   100000
#define MAXNB  50

// GEMM tiling: 128x256 tile, K split into 2 chunks of 128 halves (256B/row),
// both chunks resident in smem (no ring), cp.async.bulk + mbarrier feed.
#define BM 128
#define BN 256
#define BKC 128
#define KP 136
#define ROW_BYTES 256
#define A_STG (BM * KP * 2)
#define B_STG (BN * KP * 2)
#define STG_BYTES (A_STG + B_STG)
#define SM_CTRL 128
#define SMEM_BYTES (SM_CTRL + 2 * STG_BYTES)

#define QSCALE 524288.0f
#define RSCALE 512.0f
#define OSCALE 3.725290298461914e-09f

// prep dynamic smem layout (floats)
#define P_TRP   0                     // [8][512] -> reused as ctxbuf[16][256], then ec_part[2][8][256]
#define P_WSM   4096                  // [8][256]
#define P_LR    6144                  // [8][256]
#define P_WPART 8192                  // [2][8][256] -> reused as ctx_sm[8][256] (first 2048)
#define P_MDEN  12288                 // [16][2]
#define P_SC    12320                 // [8][2]
#define P_RED   12336                 // [8][8]
#define P_GSM   12400                 // [8]
#define P_TOTAL 12416                 // floats -> 49664 B
#define PREP_SMEM_BYTES (P_TOTAL * 4)

// scratch (allocation-free rule: device globals)
__device__ __align__(16) __half g_q16[B_SZ * RANK];
__device__ __align__(16) __half g_rhs16[(size_t)NENT * RANK];
__device__ __align__(16) float g_Wt[512 * 256];
__device__ __align__(16) float g_W2t[256 * 256];

__device__ __forceinline__ void mma_f16(float* c, const uint32_t* a, uint32_t b0, uint32_t b1) {
    asm volatile(
        "mma.sync.aligned.m16n8k16.row.col.f32.f16.f16.f32 "
        "{%0,%1,%2,%3}, {%4,%5,%6,%7}, {%8,%9}, {%0,%1,%2,%3};\n"
        : "+f"(c[0]), "+f"(c[1]), "+f"(c[2]), "+f"(c[3])
        : "r"(a[0]), "r"(a[1]), "r"(a[2]), "r"(a[3]), "r"(b0), "r"(b1));
}
__device__ __forceinline__ void ldsm_x4(uint32_t* r, uint32_t addr) {
    asm volatile("ldmatrix.sync.aligned.m8n8.x4.shared.b16 {%0,%1,%2,%3}, [%4];"
                 : "=r"(r[0]), "=r"(r[1]), "=r"(r[2]), "=r"(r[3]) : "r"(addr));
}
__device__ __forceinline__ void bulk_cp(uint32_t dst, const void* src, uint32_t bytes,
                                        uint32_t mbar) {
    asm volatile(
        "cp.async.bulk.shared::cluster.global.mbarrier::complete_tx::bytes "
        "[%0], [%1], %2, [%3];"
        :: "r"(dst), "l"(src), "r"(bytes), "r"(mbar) : "memory");
}
#define MBARRIER_INIT(a, cnt) \
    asm volatile("mbarrier.init.shared.b64 [%0], %1;" \
                 :: "r"((uint32_t)(a)), "r"((uint32_t)(cnt)) : "memory")
#define MBARRIER_EXPECT_TX(a, bytes) \
    asm volatile("mbarrier.arrive.expect_tx.shared.b64 _, [%0], %1;" \
                 :: "r"((uint32_t)(a)), "r"((uint32_t)(bytes)) : "memory")
#define MBARRIER_WAIT_PARITY(a, par) do {                                        \
    uint32_t _m = (uint32_t)(a), _p = (uint32_t)(par), _d;                       \
    asm volatile("{\n\t.reg .pred p;\n\t"                                        \
        "mbarrier.try_wait.parity.acquire.cta.shared::cta.b64 p, [%1], %2;\n\t"  \
        "selp.b32 %0, 1, 0, p;\n\t}" : "=r"(_d) : "r"(_m), "r"(_p) : "memory");  \
    if (!_d) {                                                                   \
        asm volatile("{\n\t.reg .pred P1;\n\t"                                   \
            "WL_%=:\n\t"                                                         \
            "mbarrier.try_wait.parity.acquire.cta.shared::cta.b64 P1, [%0], %1, 0x989680;\n\t" \
            "@P1 bra.uni WD_%=;\n\tbra.uni WL_%=;\n\tWD_%=:\n\t}"                \
            :: "r"(_m), "r"(_p) : "memory");                                     \
    }                                                                            \
} while (0)

// ---------------------------------------------------------------------------
// Kernel 0: fused transpose (W_w, W2_w) + rhs_w -> fp16 convert
// ---------------------------------------------------------------------------
#define TR_BLOCKS 768
__global__ __launch_bounds__(256) void setup_kernel(const float* __restrict__ W_w,
                                                    const float* __restrict__ W2_w,
                                                    const float* __restrict__ rhs_w) {
    if (blockIdx.x < TR_BLOCKS) {
        int idx = blockIdx.x * 256 + threadIdx.x;
        if (idx < 512 * 256) {
            int i = idx >> 8, j = idx & 255;
            g_Wt[idx] = W_w[j * 512 + i];
        } else {
            int idx2 = idx - 512 * 256;
            if (idx2 < 256 * 256) {
                int k = idx2 >> 8, j = idx2 & 255;
                g_W2t[idx2] = W2_w[j * 256 + k];
            }
        }
        return;
    }
    size_t i8 = ((size_t)(blockIdx.x - TR_BLOCKS) * 256 + threadIdx.x) * 8;
    if (i8 >= (size_t)NENT * RANK) return;
    float4 v0 = *reinterpret_cast<const float4*>(rhs_w + i8);
    float4 v1 = *reinterpret_cast<const float4*>(rhs_w + i8 + 4);
    __half2 h[4];
    h[0] = __floats2half2_rn(v0.x * RSCALE, v0.y * RSCALE);
    h[1] = __floats2half2_rn(v0.z * RSCALE, v0.w * RSCALE);
    h[2] = __floats2half2_rn(v1.x * RSCALE, v1.y * RSCALE);
    h[3] = __floats2half2_rn(v1.z * RSCALE, v1.w * RSCALE);
    *reinterpret_cast<uint4*>(g_rhs16 + i8) = *reinterpret_cast<uint4*>(h);
}

// ---------------------------------------------------------------------------
// Kernel 1: prep — 512 threads, split-K matvecs, 2-warp-per-row attention
// ---------------------------------------------------------------------------
__global__ __launch_bounds__(512) void prep_kernel(
    const int* __restrict__ x, const int* __restrict__ nb_idx,
    const float* __restrict__ lhs_w, const float* __restrict__ rel_w,
    const float* __restrict__ rhs_w,
    const float* __restrict__ W_b, const float* __restrict__ W2_b,
    const float* __restrict__ Wo_w, const float* __restrict__ Wo_b,
    const float* __restrict__ Uo_w, const float* __restrict__ Uo_b,
    float* __restrict__ aux)
{
    extern __shared__ float sm[];
    float* trp    = sm + P_TRP;     // [8][512]; later ctxbuf[16][256]; later ec_part[2][8][256]
    float* w_sm   = sm + P_WSM;     // [8][256]
    float* lr_sm  = sm + P_LR;      // [8][256]
    float* w_part = sm + P_WPART;   // [2][8][256]; later ctx_sm[8][256]
    float* mden   = sm + P_MDEN;    // [16][2]
    float* scb    = sm + P_SC;      // [8][2]
    float* red    = sm + P_RED;     // [8][8]
    float* g_sm   = sm + P_GSM;     // [8]

    const int tid = threadIdx.x;
    const int b0 = blockIdx.x * 8;
    const int lane = tid & 31;
    const int warp = tid >> 5;
    const int grp = tid >> 8;       // 0 or 1
    const int t2 = tid & 255;

    // phase 1: gathers (group g handles rows g*4..g*4+3)
#pragma unroll
    for (int r = 0; r < 4; r++) {
        int bb = grp * 4 + r;
        int b = b0 + bb;
        int i0 = x[b * 3 + 0];
        int i1 = x[b * 3 + 1];
        int i2 = x[b * 3 + 2];
        float lv = lhs_w[(size_t)i0 * RANK + t2];
        float rv = rel_w[(size_t)i1 * RANK + t2];
        float hv = rhs_w[(size_t)i2 * RANK + t2];
        trp[bb * 512 + t2]       = lv;
        trp[bb * 512 + 256 + t2] = rv;
        lr_sm[bb * 256 + t2] = lv * rv;
        if (aux) {
            aux[(size_t)b * RANK + t2]              = lv;
            aux[262144 + (size_t)b * RANK + t2]     = rv;
            aux[2 * 262144 + (size_t)b * RANK + t2] = hv;
        }
    }
    __syncthreads();

    // phase 2: w-matvec, i-range split across groups
    {
        float acc[8];
#pragma unroll
        for (int bb = 0; bb < 8; bb++) acc[bb] = 0.f;
        const int i0 = grp * 256;
        for (int i = i0; i < i0 + 256; i += 4) {
            float wv0 = g_Wt[(i + 0) * 256 + t2];
            float wv1 = g_Wt[(i + 1) * 256 + t2];
            float wv2 = g_Wt[(i + 2) * 256 + t2];
            float wv3 = g_Wt[(i + 3) * 256 + t2];
#pragma unroll
            for (int bb = 0; bb < 8; bb++) {
                const float4 tv = *reinterpret_cast<const float4*>(&trp[bb * 512 + i]);
                acc[bb] += wv0 * tv.x + wv1 * tv.y + wv2 * tv.z + wv3 * tv.w;
            }
        }
#pragma unroll
        for (int bb = 0; bb < 8; bb++) w_part[(grp * 8 + bb) * 256 + t2] = acc[bb];
    }
    __syncthreads();
    if (tid < 256) {
        float bias = W_b[t2];
#pragma unroll
        for (int bb = 0; bb < 8; bb++)
            w_sm[bb * 256 + t2] = w_part[bb * 256 + t2] + w_part[(8 + bb) * 256 + t2] + bias;
    }
    __syncthreads();

    // phase 3: attention, 2 warps per row, 25 neighbors each, online softmax
    {
        const int bb = warp >> 1;
        const int h = warp & 1;
        const int b = b0 + bb;
        float wreg[8];
#pragma unroll
        for (int j = 0; j < 8; j++) wreg[j] = w_sm[bb * 256 + lane + 32 * j];
        float ctx_acc[8];
#pragma unroll
        for (int j = 0; j < 8; j++) ctx_acc[j] = 0.f;
        float Mx = -1e30f, den = 0.f;
        const int mbase = b * MAXNB + h * 25;
        for (int m = 0; m < 25; m++) {
            int nb = __ldg(&nb_idx[mbase + m]);
            const float* r = rhs_w + (size_t)nb * RANK;
            float rv[8];
            float s = 0.f;
#pragma unroll
            for (int j = 0; j < 8; j++) {
                rv[j] = __ldg(&r[lane + 32 * j]);
                s += wreg[j] * rv[j];
            }
#pragma unroll
            for (int o = 16; o > 0; o >>= 1) s += __shfl_xor_sync(0xffffffffu, s, o);
            float Mn = fmaxf(Mx, s);
            float scale = __expf(Mx - Mn);
            float p = __expf(s - Mn);
            den = den * scale + p;
#pragma unroll
            for (int j = 0; j < 8; j++) ctx_acc[j] = ctx_acc[j] * scale + p * rv[j];
            Mx = Mn;
        }
        // trp space now reused as ctxbuf[16][256]
#pragma unroll
        for (int j = 0; j < 8; j++) trp[warp * 256 + lane + 32 * j] = ctx_acc[j];
        if (lane == 0) { mden[warp * 2 + 0] = Mx; mden[warp * 2 + 1] = den; }
    }
    __syncthreads();
    // merge halves: t<8 computes per-row scales
    if (tid < 8) {
        float M0 = mden[(2 * tid) * 2 + 0],     d0 = mden[(2 * tid) * 2 + 1];
        float M1 = mden[(2 * tid + 1) * 2 + 0], d1 = mden[(2 * tid + 1) * 2 + 1];
        float M = fmaxf(M0, M1);
        float s0 = __expf(M0 - M), s1 = __expf(M1 - M);
        float inv = 1.f / (d0 * s0 + d1 * s1);
        scb[tid * 2 + 0] = s0 * inv;
        scb[tid * 2 + 1] = s1 * inv;
    }
    __syncthreads();
    // ctx_sm (w_part space) = merged context
#pragma unroll
    for (int p = 0; p < 4; p++) {
        int idx = tid + p * 512;
        int bb = idx >> 8, t = idx & 255;
        w_part[bb * 256 + t] = trp[(2 * bb) * 256 + t] * scb[bb * 2 + 0]
                             + trp[(2 * bb + 1) * 256 + t] * scb[bb * 2 + 1];
    }
    __syncthreads();

    // phase 5: e_c matvec, k-range split across groups (ec_part in trp space)
    {
        float acc[8];
#pragma unroll
        for (int bb = 0; bb < 8; bb++) acc[bb] = 0.f;
        const int k0 = grp * 128;
        for (int k = k0; k < k0 + 128; k += 4) {
            float w0 = g_W2t[(k + 0) * 256 + t2];
            float w1 = g_W2t[(k + 1) * 256 + t2];
            float w2 = g_W2t[(k + 2) * 256 + t2];
            float w3 = g_W2t[(k + 3) * 256 + t2];
#pragma unroll
            for (int bb = 0; bb < 8; bb++) {
                const float4 cv = *reinterpret_cast<const float4*>(&w_part[bb * 256 + k]);
                acc[bb] += w0 * cv.x + w1 * cv.y + w2 * cv.z + w3 * cv.w;
            }
        }
#pragma unroll
        for (int bb = 0; bb < 8; bb++) trp[(grp * 8 + bb) * 256 + t2] = acc[bb];
    }
    __syncthreads();

    float ec[8];
    if (tid < 256) {
        float bias = W2_b[t2];
#pragma unroll
        for (int bb = 0; bb < 8; bb++) {
            ec[bb] = trp[bb * 256 + t2] + trp[(8 + bb) * 256 + t2] + bias;
            if (aux) aux[3 * 262144 + (size_t)(b0 + bb) * RANK + t2] = ec[bb];
        }
        // gate contributions (warps 0-7)
        float uo = Uo_w[t2], wo = Wo_w[t2];
#pragma unroll
        for (int bb = 0; bb < 8; bb++) {
            float c = uo * lr_sm[bb * 256 + t2] + wo * ec[bb];
#pragma unroll
            for (int o = 16; o > 0; o >>= 1) c += __shfl_xor_sync(0xffffffffu, c, o);
            if (lane == 0) red[bb * 8 + warp] = c;
        }
    }
    __syncthreads();
    if (tid < 8) {
        float s = 0.f;
#pragma unroll
        for (int w = 0; w < 8; w++) s += red[tid * 8 + w];
        s += Uo_b[0] + Wo_b[0];
        g_sm[tid] = 1.f / (1.f + expf(-s));
    }
    __syncthreads();

    if (tid < 256) {
#pragma unroll
        for (int bb = 0; bb < 8; bb++) {
            float g = g_sm[bb];
            float q = lr_sm[bb * 256 + t2] * (g * ec[bb] + 1.f - g);
            g_q16[(size_t)(b0 + bb) * RANK + t2] = __float2half_rn(q * QSCALE);
        }
    }
}

// ---------------------------------------------------------------------------
// Kernel 2: fp16 GEMM (unchanged from R8): 128x256, bulk-copy 2-chunk feed.
// ---------------------------------------------------------------------------
__global__ __launch_bounds__(256, 1) void gemm_f16_kernel(float* __restrict__ out)
{
    extern __shared__ __half smem[];

    const int tid = threadIdx.x;
    const int m0 = blockIdx.x * BM;
    const int n0 = blockIdx.y * BN;
    const int lane = tid & 31;
    const int warp = tid >> 5;
    const int wm = warp & 1;
    const int wn = warp >> 1;
    const int gid = lane >> 2;
    const int qid = lane & 3;

    const uint32_t smem_u32 = (uint32_t)__cvta_generic_to_shared(smem);
    const uint32_t mbar0 = smem_u32;
    const int vb = min(BN, NENT - n0);

    if (tid == 0) {
        MBARRIER_INIT(mbar0 + 0, 1);
        MBARRIER_INIT(mbar0 + 8, 1);
    }
    if (vb < BN) {
        int zrows = BN - vb;
        for (int i = tid; i < zrows * (KP / 8) * 2; i += 256) {
            int st = i / (zrows * (KP / 8));
            int r = (i / (KP / 8)) % zrows;
            int c = i % (KP / 8);
            uint32_t a = smem_u32 + SM_CTRL + st * STG_BYTES + A_STG
                       + (uint32_t)((vb + r) * KP * 2 + c * 16);
            asm volatile("st.shared.v4.b32 [%0], {%1,%1,%1,%1};" :: "r"(a), "r"(0) : "memory");
        }
    }
    __syncthreads();
    if (tid == 0) {
        MBARRIER_EXPECT_TX(mbar0 + 0, (uint32_t)(BM + vb) * ROW_BYTES);
        MBARRIER_EXPECT_TX(mbar0 + 8, (uint32_t)(BM + vb) * ROW_BYTES);
    }
    __syncthreads();

#pragma unroll
    for (int ch = 0; ch < 2; ch++) {
        const uint32_t sb = smem_u32 + SM_CTRL + ch * STG_BYTES;
        const uint32_t mb = mbar0 + ch * 8;
        if (tid < BM)
            bulk_cp(sb + (uint32_t)(tid * KP * 2),
                    g_q16 + (size_t)(m0 + tid) * RANK + ch * BKC, ROW_BYTES, mb);
        if (tid < vb)
            bulk_cp(sb + A_STG + (uint32_t)(tid * KP * 2),
                    g_rhs16 + (size_t)(n0 + tid) * RANK + ch * BKC, ROW_BYTES, mb);
    }

    float acc[4][8][4];
#pragma unroll
    for (int i = 0; i < 4; i++)
#pragma unroll
        for (int tn = 0; tn < 8; tn++)
#pragma unroll
            for (int r = 0; r < 4; r++) acc[i][tn][r] = 0.f;

    const int lrow = lane & 15;
    const int lcol16 = (lane >> 4) * 16;

#pragma unroll
    for (int ch = 0; ch < 2; ch++) {
        MBARRIER_WAIT_PARITY(mbar0 + ch * 8, 0);
        const uint32_t abase = smem_u32 + SM_CTRL + ch * STG_BYTES;
        const uint32_t bbase = abase + A_STG;

#pragma unroll
        for (int kk = 0; kk < BKC / 16; kk++) {
            uint32_t a[4][4];
#pragma unroll
            for (int i = 0; i < 4; i++)
                ldsm_x4(a[i], abase + (uint32_t)((wm * 64 + i * 16 + lrow) * (KP * 2)
                                                 + kk * 32 + lcol16));
            uint32_t b[4][4];
#pragma unroll
            for (int j = 0; j < 4; j++)
                ldsm_x4(b[j], bbase + (uint32_t)((wn * 64 + j * 16 + lrow) * (KP * 2)
                                                 + kk * 32 + lcol16));
#pragma unroll
            for (int i = 0; i < 4; i++)
#pragma unroll
                for (int tn = 0; tn < 8; tn++) {
                    int j = tn >> 1, h = tn & 1;
                    mma_f16(acc[i][tn], a[i], b[j][h], b[j][h + 2]);
                }
        }
    }

#pragma unroll
    for (int i = 0; i < 4; i++) {
        int r = m0 + wm * 64 + i * 16 + gid;
#pragma unroll
        for (int tn = 0; tn < 8; tn++) {
            int cb = n0 + wn * 64 + tn * 8 + 2 * qid;
            if (cb < NENT) {
                __stcs(reinterpret_cast<float2*>(out + (size_t)r * NENT + cb),
                       make_float2(acc[i][tn][0] * OSCALE, acc[i][tn][1] * OSCALE));
                __stcs(reinterpret_cast<float2*>(out + (size_t)(r + 8) * NENT + cb),
                       make_float2(acc[i][tn][2] * OSCALE, acc[i][tn][3] * OSCALE));
            }
        }
    }
}

// ---------------------------------------------------------------------------
extern "C" void kernel_launch(void* const* d_in, const int* in_sizes, int n_in,
                              void* d_out, int out_size) {
    const int*   x      = (const int*)d_in[0];
    const int*   nb     = (const int*)d_in[1];
    const float* lhs_w  = (const float*)d_in[2];
    const float* rel_w  = (const float*)d_in[3];
    const float* rhs_w  = (const float*)d_in[4];
    const float* W_w    = (const float*)d_in[5];
    const float* W_b    = (const float*)d_in[6];
    const float* W2_w   = (const float*)d_in[7];
    const float* W2_b   = (const float*)d_in[8];
    const float* Wo_w   = (const float*)d_in[9];
    const float* Wo_b   = (const float*)d_in[10];
    const float* Uo_w   = (const float*)d_in[11];
    const float* Uo_b   = (const float*)d_in[12];
    float* out = (float*)d_out;

    float* aux = nullptr;
    if (out_size >= 102400000 + 4 * 262144) aux = out + 102400000;

    static bool attr_set = false;
    if (!attr_set) {
        cudaFuncSetAttribute(gemm_f16_kernel,
                             cudaFuncAttributeMaxDynamicSharedMemorySize, SMEM_BYTES);
        cudaFuncSetAttribute(prep_kernel,
                             cudaFuncAttributeMaxDynamicSharedMemorySize, PREP_SMEM_BYTES);
        attr_set = true;
    }

    int conv_blocks = (NENT * RANK / 8 + 255) / 256;
    setup_kernel<<<TR_BLOCKS + conv_blocks, 256>>>(W_w, W2_w, rhs_w);
    prep_kernel<<<B_SZ / 8, 512, PREP_SMEM_BYTES>>>(x, nb, lhs_w, rel_w, rhs_w,
                                                    W_b, W2_b, Wo_w, Wo_b, Uo_w, Uo_b, aux);
    dim3 grid(B_SZ / BM, (NENT + BN - 1) / BN);
    gemm_f16_kernel<<<grid, 256, SMEM_BYTES>>>(out);
}

// round 10
// speedup vs baseline: 1.8111x; 1.0695x over previous
#include <cuda_runtime.h>
#include <cuda_fp16.h>
#include <cstdint>
#include <math.h>

#define B_SZ   1024
#define RANK   256
#define NENT   100000
#define MAXNB  50

// GEMM tiling: 128x256 tile, K = 2 chunks of 128 halves, 2-stage ring that
// flows ACROSS tiles (persistent CTAs), cp.async.bulk + mbarrier feed.
#define BM 128
#define BN 256
#define BKC 128
#define KP 136
#define ROW_BYTES 256
#define A_STG (BM * KP * 2)
#define B_STG (BN * KP * 2)
#define STG_BYTES (A_STG + B_STG)
#define SM_CTRL 128
#define SMEM_BYTES (SM_CTRL + 2 * STG_BYTES)
#define NT (8 * 391)                  // 3128 tiles, m fastest
#define CHUNK_TX ((BM + BN) * ROW_BYTES)   // 98304 bytes per chunk

#define QSCALE 524288.0f
#define RSCALE 512.0f
#define OSCALE 3.725290298461914e-09f

// prep dynamic smem layout (floats)
#define P_TRP   0
#define P_WSM   4096
#define P_LR    6144
#define P_WPART 8192
#define P_MDEN  12288
#define P_SC    12320
#define P_RED   12336
#define P_GSM   12400
#define P_TOTAL 12416
#define PREP_SMEM_BYTES (P_TOTAL * 4)
#define PREP_BLOCKS 128

// scratch (allocation-free rule: device globals)
__device__ __align__(16) __half g_q16[B_SZ * RANK];
__device__ __align__(16) __half g_rhs16[(size_t)NENT * RANK];

__device__ __forceinline__ void mma_f16(float* c, const uint32_t* a, uint32_t b0, uint32_t b1) {
    asm volatile(
        "mma.sync.aligned.m16n8k16.row.col.f32.f16.f16.f32 "
        "{%0,%1,%2,%3}, {%4,%5,%6,%7}, {%8,%9}, {%0,%1,%2,%3};\n"
        : "+f"(c[0]), "+f"(c[1]), "+f"(c[2]), "+f"(c[3])
        : "r"(a[0]), "r"(a[1]), "r"(a[2]), "r"(a[3]), "r"(b0), "r"(b1));
}
__device__ __forceinline__ void ldsm_x4(uint32_t* r, uint32_t addr) {
    asm volatile("ldmatrix.sync.aligned.m8n8.x4.shared.b16 {%0,%1,%2,%3}, [%4];"
                 : "=r"(r[0]), "=r"(r[1]), "=r"(r[2]), "=r"(r[3]) : "r"(addr));
}
__device__ __forceinline__ void bulk_cp(uint32_t dst, const void* src, uint32_t bytes,
                                        uint32_t mbar) {
    asm volatile(
        "cp.async.bulk.shared::cluster.global.mbarrier::complete_tx::bytes "
        "[%0], [%1], %2, [%3];"
        :: "r"(dst), "l"(src), "r"(bytes), "r"(mbar) : "memory");
}
#define MBARRIER_INIT(a, cnt) \
    asm volatile("mbarrier.init.shared.b64 [%0], %1;" \
                 :: "r"((uint32_t)(a)), "r"((uint32_t)(cnt)) : "memory")
#define MBARRIER_EXPECT_TX(a, bytes) \
    asm volatile("mbarrier.arrive.expect_tx.shared.b64 _, [%0], %1;" \
                 :: "r"((uint32_t)(a)), "r"((uint32_t)(bytes)) : "memory")
#define MBARRIER_WAIT_PARITY(a, par) do {                                        \
    uint32_t _m = (uint32_t)(a), _p = (uint32_t)(par), _d;                       \
    asm volatile("{\n\t.reg .pred p;\n\t"                                        \
        "mbarrier.try_wait.parity.acquire.cta.shared::cta.b64 p, [%1], %2;\n\t"  \
        "selp.b32 %0, 1, 0, p;\n\t}" : "=r"(_d) : "r"(_m), "r"(_p) : "memory");  \
    if (!_d) {                                                                   \
        asm volatile("{\n\t.reg .pred P1;\n\t"                                   \
            "WL_%=:\n\t"                                                         \
            "mbarrier.try_wait.parity.acquire.cta.shared::cta.b64 P1, [%0], %1, 0x989680;\n\t" \
            "@P1 bra.uni WD_%=;\n\tbra.uni WL_%=;\n\tWD_%=:\n\t}"                \
            :: "r"(_m), "r"(_p) : "memory");                                     \
    }                                                                            \
} while (0)

// ---------------------------------------------------------------------------
// Kernel 1: fused prep (blocks < PREP_BLOCKS) + rhs convert (blocks >=).
// prep reads W_w / W2_w rows directly (L2-resident) -> no transpose kernel.
// ---------------------------------------------------------------------------
__global__ __launch_bounds__(512) void prep_kernel(
    const int* __restrict__ x, const int* __restrict__ nb_idx,
    const float* __restrict__ lhs_w, const float* __restrict__ rel_w,
    const float* __restrict__ rhs_w,
    const float* __restrict__ W_w, const float* __restrict__ W_b,
    const float* __restrict__ W2_w, const float* __restrict__ W2_b,
    const float* __restrict__ Wo_w, const float* __restrict__ Wo_b,
    const float* __restrict__ Uo_w, const float* __restrict__ Uo_b,
    float* __restrict__ aux)
{
    if (blockIdx.x >= PREP_BLOCKS) {
        // convert path: 4096 elems per block
        size_t i8 = (((size_t)(blockIdx.x - PREP_BLOCKS)) * 512 + threadIdx.x) * 8;
        if (i8 < (size_t)NENT * RANK) {
            float4 v0 = *reinterpret_cast<const float4*>(rhs_w + i8);
            float4 v1 = *reinterpret_cast<const float4*>(rhs_w + i8 + 4);
            __half2 h[4];
            h[0] = __floats2half2_rn(v0.x * RSCALE, v0.y * RSCALE);
            h[1] = __floats2half2_rn(v0.z * RSCALE, v0.w * RSCALE);
            h[2] = __floats2half2_rn(v1.x * RSCALE, v1.y * RSCALE);
            h[3] = __floats2half2_rn(v1.z * RSCALE, v1.w * RSCALE);
            *reinterpret_cast<uint4*>(g_rhs16 + i8) = *reinterpret_cast<uint4*>(h);
        }
        return;
    }

    extern __shared__ float sm[];
    float* trp    = sm + P_TRP;     // [8][512]; later ctxbuf[16][256]; later ec_part
    float* w_sm   = sm + P_WSM;
    float* lr_sm  = sm + P_LR;
    float* w_part = sm + P_WPART;   // [2][8][256]; later ctx_sm[8][256]
    float* mden   = sm + P_MDEN;
    float* scb    = sm + P_SC;
    float* red    = sm + P_RED;
    float* g_sm   = sm + P_GSM;

    const int tid = threadIdx.x;
    const int b0 = blockIdx.x * 8;
    const int lane = tid & 31;
    const int warp = tid >> 5;
    const int grp = tid >> 8;
    const int t2 = tid & 255;

    // phase 1: gathers
#pragma unroll
    for (int r = 0; r < 4; r++) {
        int bb = grp * 4 + r;
        int b = b0 + bb;
        int i0 = x[b * 3 + 0];
        int i1 = x[b * 3 + 1];
        int i2 = x[b * 3 + 2];
        float lv = lhs_w[(size_t)i0 * RANK + t2];
        float rv = rel_w[(size_t)i1 * RANK + t2];
        float hv = rhs_w[(size_t)i2 * RANK + t2];
        trp[bb * 512 + t2]       = lv;
        trp[bb * 512 + 256 + t2] = rv;
        lr_sm[bb * 256 + t2] = lv * rv;
        if (aux) {
            aux[(size_t)b * RANK + t2]              = lv;
            aux[262144 + (size_t)b * RANK + t2]     = rv;
            aux[2 * 262144 + (size_t)b * RANK + t2] = hv;
        }
    }
    __syncthreads();

    // phase 2: w-matvec, direct W_w rows, i-range split across groups
    {
        float acc[8];
#pragma unroll
        for (int bb = 0; bb < 8; bb++) acc[bb] = 0.f;
        const float* wrow = W_w + (size_t)t2 * 512 + grp * 256;
        for (int i = 0; i < 256; i += 4) {
            float4 wv = *reinterpret_cast<const float4*>(wrow + i);
#pragma unroll
            for (int bb = 0; bb < 8; bb++) {
                const float4 tv = *reinterpret_cast<const float4*>(&trp[bb * 512 + grp * 256 + i]);
                acc[bb] += wv.x * tv.x + wv.y * tv.y + wv.z * tv.z + wv.w * tv.w;
            }
        }
#pragma unroll
        for (int bb = 0; bb < 8; bb++) w_part[(grp * 8 + bb) * 256 + t2] = acc[bb];
    }
    __syncthreads();
    if (tid < 256) {
        float bias = W_b[t2];
#pragma unroll
        for (int bb = 0; bb < 8; bb++)
            w_sm[bb * 256 + t2] = w_part[bb * 256 + t2] + w_part[(8 + bb) * 256 + t2] + bias;
    }
    __syncthreads();

    // phase 3: attention, 2 warps per row, 25 neighbors each, online softmax
    {
        const int bb = warp >> 1;
        const int h = warp & 1;
        const int b = b0 + bb;
        float wreg[8];
#pragma unroll
        for (int j = 0; j < 8; j++) wreg[j] = w_sm[bb * 256 + lane + 32 * j];
        float ctx_acc[8];
#pragma unroll
        for (int j = 0; j < 8; j++) ctx_acc[j] = 0.f;
        float Mx = -1e30f, den = 0.f;
        const int mbase = b * MAXNB + h * 25;
        for (int m = 0; m < 25; m++) {
            int nb = __ldg(&nb_idx[mbase + m]);
            const float* r = rhs_w + (size_t)nb * RANK;
            float rv[8];
            float s = 0.f;
#pragma unroll
            for (int j = 0; j < 8; j++) {
                rv[j] = __ldg(&r[lane + 32 * j]);
                s += wreg[j] * rv[j];
            }
#pragma unroll
            for (int o = 16; o > 0; o >>= 1) s += __shfl_xor_sync(0xffffffffu, s, o);
            float Mn = fmaxf(Mx, s);
            float scale = __expf(Mx - Mn);
            float p = __expf(s - Mn);
            den = den * scale + p;
#pragma unroll
            for (int j = 0; j < 8; j++) ctx_acc[j] = ctx_acc[j] * scale + p * rv[j];
            Mx = Mn;
        }
#pragma unroll
        for (int j = 0; j < 8; j++) trp[warp * 256 + lane + 32 * j] = ctx_acc[j];
        if (lane == 0) { mden[warp * 2 + 0] = Mx; mden[warp * 2 + 1] = den; }
    }
    __syncthreads();
    if (tid < 8) {
        float M0 = mden[(2 * tid) * 2 + 0],     d0 = mden[(2 * tid) * 2 + 1];
        float M1 = mden[(2 * tid + 1) * 2 + 0], d1 = mden[(2 * tid + 1) * 2 + 1];
        float M = fmaxf(M0, M1);
        float s0 = __expf(M0 - M), s1 = __expf(M1 - M);
        float inv = 1.f / (d0 * s0 + d1 * s1);
        scb[tid * 2 + 0] = s0 * inv;
        scb[tid * 2 + 1] = s1 * inv;
    }
    __syncthreads();
#pragma unroll
    for (int p = 0; p < 4; p++) {
        int idx = tid + p * 512;
        int bb = idx >> 8, t = idx & 255;
        w_part[bb * 256 + t] = trp[(2 * bb) * 256 + t] * scb[bb * 2 + 0]
                             + trp[(2 * bb + 1) * 256 + t] * scb[bb * 2 + 1];
    }
    __syncthreads();

    // phase 5: e_c matvec, direct W2_w rows, k-range split across groups
    {
        float acc[8];
#pragma unroll
        for (int bb = 0; bb < 8; bb++) acc[bb] = 0.f;
        const float* w2row = W2_w + (size_t)t2 * 256 + grp * 128;
        for (int k = 0; k < 128; k += 4) {
            float4 wv = *reinterpret_cast<const float4*>(w2row + k);
#pragma unroll
            for (int bb = 0; bb < 8; bb++) {
                const float4 cv = *reinterpret_cast<const float4*>(&w_part[bb * 256 + grp * 128 + k]);
                acc[bb] += wv.x * cv.x + wv.y * cv.y + wv.z * cv.z + wv.w * cv.w;
            }
        }
#pragma unroll
        for (int bb = 0; bb < 8; bb++) trp[(grp * 8 + bb) * 256 + t2] = acc[bb];
    }
    __syncthreads();

    float ec[8];
    if (tid < 256) {
        float bias = W2_b[t2];
#pragma unroll
        for (int bb = 0; bb < 8; bb++) {
            ec[bb] = trp[bb * 256 + t2] + trp[(8 + bb) * 256 + t2] + bias;
            if (aux) aux[3 * 262144 + (size_t)(b0 + bb) * RANK + t2] = ec[bb];
        }
        float uo = Uo_w[t2], wo = Wo_w[t2];
#pragma unroll
        for (int bb = 0; bb < 8; bb++) {
            float c = uo * lr_sm[bb * 256 + t2] + wo * ec[bb];
#pragma unroll
            for (int o = 16; o > 0; o >>= 1) c += __shfl_xor_sync(0xffffffffu, c, o);
            if (lane == 0) red[bb * 8 + warp] = c;
        }
    }
    __syncthreads();
    if (tid < 8) {
        float s = 0.f;
#pragma unroll
        for (int w = 0; w < 8; w++) s += red[tid * 8 + w];
        s += Uo_b[0] + Wo_b[0];
        g_sm[tid] = 1.f / (1.f + expf(-s));
    }
    __syncthreads();
    if (tid < 256) {
#pragma unroll
        for (int bb = 0; bb < 8; bb++) {
            float g = g_sm[bb];
            float q = lr_sm[bb * 256 + t2] * (g * ec[bb] + 1.f - g);
            g_q16[(size_t)(b0 + bb) * RANK + t2] = __float2half_rn(q * QSCALE);
        }
    }
}

// ---------------------------------------------------------------------------
// Kernel 2: persistent fp16 GEMM. grid = #SMs; each CTA loops tiles (m fastest)
// with a 2-stage chunk ring flowing across tiles (stage = chunk parity,
// mbarrier phase = local-tile parity). Row-clamped edge loads, no zero-fill.
// ---------------------------------------------------------------------------
__global__ __launch_bounds__(256, 1) void gemm_f16_kernel(float* __restrict__ out)
{
    extern __shared__ __half smem[];

    const int tid = threadIdx.x;
    const int lane = tid & 31;
    const int warp = tid >> 5;
    const int wm = warp & 1;
    const int wn = warp >> 1;
    const int gid = lane >> 2;
    const int qid = lane & 3;
    const int lrow = lane & 15;
    const int lcol16 = (lane >> 4) * 16;

    const uint32_t smem_u32 = (uint32_t)__cvta_generic_to_shared(smem);
    const uint32_t mbar0 = smem_u32;

    const int nct = gridDim.x;
    const int nloc = (NT - (int)blockIdx.x + nct - 1) / nct;
    if (nloc <= 0) return;
    const int Ltot = 2 * nloc;

    if (tid == 0) {
        MBARRIER_INIT(mbar0 + 0, 1);
        MBARRIER_INIT(mbar0 + 8, 1);
        MBARRIER_EXPECT_TX(mbar0 + 0, CHUNK_TX);
        if (Ltot > 1) MBARRIER_EXPECT_TX(mbar0 + 8, CHUNK_TX);
    }
    __syncthreads();

    auto issue_chunk = [&](int L) {          // chunk L -> stage L&1
        const int li = L >> 1, ch = L & 1;
        const int t = (int)blockIdx.x + li * nct;
        const int m0 = (t & 7) * BM;
        const int n0 = (t >> 3) * BN;
        const uint32_t sb = smem_u32 + SM_CTRL + (uint32_t)(ch * STG_BYTES);
        const uint32_t mb = mbar0 + ch * 8;
        if (tid < BM)
            bulk_cp(sb + (uint32_t)(tid * KP * 2),
                    g_q16 + (size_t)(m0 + tid) * RANK + ch * BKC, ROW_BYTES, mb);
        int nr = n0 + tid;
        if (nr > NENT - 1) nr = NENT - 1;    // clamp (dup rows, never stored)
        bulk_cp(sb + A_STG + (uint32_t)(tid * KP * 2),
                g_rhs16 + (size_t)nr * RANK + ch * BKC, ROW_BYTES, mb);
    };

    issue_chunk(0);
    if (Ltot > 1) issue_chunk(1);

#pragma unroll 1
    for (int li = 0; li < nloc; li++) {
        const int t = (int)blockIdx.x + li * nct;
        const int m0 = (t & 7) * BM;
        const int n0 = (t >> 3) * BN;

        float acc[4][8][4];
#pragma unroll
        for (int i = 0; i < 4; i++)
#pragma unroll
            for (int tn = 0; tn < 8; tn++)
#pragma unroll
                for (int r = 0; r < 4; r++) acc[i][tn][r] = 0.f;

#pragma unroll 1
        for (int ch = 0; ch < 2; ch++) {
            const int L = li * 2 + ch;
            MBARRIER_WAIT_PARITY(mbar0 + ch * 8, li & 1);

            const uint32_t abase = smem_u32 + SM_CTRL + (uint32_t)(ch * STG_BYTES);
            const uint32_t bbase = abase + A_STG;
#pragma unroll
            for (int kk = 0; kk < BKC / 16; kk++) {
                uint32_t a[4][4];
#pragma unroll
                for (int i = 0; i < 4; i++)
                    ldsm_x4(a[i], abase + (uint32_t)((wm * 64 + i * 16 + lrow) * (KP * 2)
                                                     + kk * 32 + lcol16));
                uint32_t b[4][4];
#pragma unroll
                for (int j = 0; j < 4; j++)
                    ldsm_x4(b[j], bbase + (uint32_t)((wn * 64 + j * 16 + lrow) * (KP * 2)
                                                     + kk * 32 + lcol16));
#pragma unroll
                for (int i = 0; i < 4; i++)
#pragma unroll
                    for (int tn = 0; tn < 8; tn++) {
                        int j = tn >> 1, h = tn & 1;
                        mma_f16(acc[i][tn], a[i], b[j][h], b[j][h + 2]);
                    }
            }

            if (L + 2 < Ltot) {
                __syncthreads();             // all warps done reading stage ch
                if (tid == 0) MBARRIER_EXPECT_TX(mbar0 + ch * 8, CHUNK_TX);
                __syncthreads();
                issue_chunk(L + 2);          // next tile's loads overlap epilogue
            }
        }

        // epilogue: descale + streaming stores
#pragma unroll
        for (int i = 0; i < 4; i++) {
            int r = m0 + wm * 64 + i * 16 + gid;
#pragma unroll
            for (int tn = 0; tn < 8; tn++) {
                int cb = n0 + wn * 64 + tn * 8 + 2 * qid;
                if (cb < NENT) {
                    __stcs(reinterpret_cast<float2*>(out + (size_t)r * NENT + cb),
                           make_float2(acc[i][tn][0] * OSCALE, acc[i][tn][1] * OSCALE));
                    __stcs(reinterpret_cast<float2*>(out + (size_t)(r + 8) * NENT + cb),
                           make_float2(acc[i][tn][2] * OSCALE, acc[i][tn][3] * OSCALE));
                }
            }
        }
    }
}

// ---------------------------------------------------------------------------
extern "C" void kernel_launch(void* const* d_in, const int* in_sizes, int n_in,
                              void* d_out, int out_size) {
    const int*   x      = (const int*)d_in[0];
    const int*   nb     = (const int*)d_in[1];
    const float* lhs_w  = (const float*)d_in[2];
    const float* rel_w  = (const float*)d_in[3];
    const float* rhs_w  = (const float*)d_in[4];
    const float* W_w    = (const float*)d_in[5];
    const float* W_b    = (const float*)d_in[6];
    const float* W2_w   = (const float*)d_in[7];
    const float* W2_b   = (const float*)d_in[8];
    const float* Wo_w   = (const float*)d_in[9];
    const float* Wo_b   = (const float*)d_in[10];
    const float* Uo_w   = (const float*)d_in[11];
    const float* Uo_b   = (const float*)d_in[12];
    float* out = (float*)d_out;

    float* aux = nullptr;
    if (out_size >= 102400000 + 4 * 262144) aux = out + 102400000;

    static int nsm = 0;
    if (!nsm) {
        cudaFuncSetAttribute(gemm_f16_kernel,
                             cudaFuncAttributeMaxDynamicSharedMemorySize, SMEM_BYTES);
        cudaFuncSetAttribute(prep_kernel,
                             cudaFuncAttributeMaxDynamicSharedMemorySize, PREP_SMEM_BYTES);
        int dev = 0;
        cudaGetDevice(&dev);
        cudaDeviceGetAttribute(&nsm, cudaDevAttrMultiProcessorCount, dev);
        if (nsm <= 0) nsm = 148;
    }

    int conv_blocks = (NENT * RANK + 4095) / 4096;   // 6250
    prep_kernel<<<PREP_BLOCKS + conv_blocks, 512, PREP_SMEM_BYTES>>>(
        x, nb, lhs_w, rel_w, rhs_w, W_w, W_b, W2_w, W2_b,
        Wo_w, Wo_b, Uo_w, Uo_b, aux);
    gemm_f16_kernel<<<nsm, 256, SMEM_BYTES>>>(out);
}

// round 11
// speedup vs baseline: 1.9347x; 1.0682x over previous
#include <cuda_runtime.h>
#include <cuda_fp16.h>
#include <cstdint>
#include <math.h>

#define B_SZ   1024
#define RANK   256
#define NENT   100000
#define MAXNB  50

// GEMM tiling: 128x256 tile, K = 2 chunks of 128 halves, 2-stage ring flowing
// across tiles (persistent CTAs), cp.async.bulk + mbarrier feed.
#define BM 128
#define BN 256
#define BKC 128
#define KP 136
#define ROW_BYTES 256
#define A_STG (BM * KP * 2)
#define B_STG (BN * KP * 2)
#define STG_BYTES (A_STG + B_STG)
#define SM_CTRL 128
#define SMEM_BYTES (SM_CTRL + 2 * STG_BYTES)   // 209024
#define NT (8 * 391)
#define NBT 391
#define CHUNK_TX ((BM + BN) * ROW_BYTES)

#define QSCALE 524288.0f
#define RSCALE 512.0f
#define OSCALE 3.725290298461914e-09f

// prep smem layout (floats, within the dynamic smem block)
#define P_TRP   0
#define P_WSM   4096
#define P_LR    6144
#define P_WPART 8192
#define P_MDEN  12288
#define P_SC    12320
#define P_RED   12336
#define P_GSM   12400
#define PREP_BLOCKS 128

// scratch + sync state (allocation-free rule: device globals)
__device__ __align__(16) __half g_q16[B_SZ * RANK];
__device__ __align__(16) __half g_rhs16[(size_t)NENT * RANK];
__device__ int g_flag_q[8];
__device__ int g_flag_b[NBT];
__device__ unsigned int g_conv_ctr;

__device__ __forceinline__ void mma_f16(float* c, const uint32_t* a, uint32_t b0, uint32_t b1) {
    asm volatile(
        "mma.sync.aligned.m16n8k16.row.col.f32.f16.f16.f32 "
        "{%0,%1,%2,%3}, {%4,%5,%6,%7}, {%8,%9}, {%0,%1,%2,%3};\n"
        : "+f"(c[0]), "+f"(c[1]), "+f"(c[2]), "+f"(c[3])
        : "r"(a[0]), "r"(a[1]), "r"(a[2]), "r"(a[3]), "r"(b0), "r"(b1));
}
__device__ __forceinline__ void ldsm_x4(uint32_t* r, uint32_t addr) {
    asm volatile("ldmatrix.sync.aligned.m8n8.x4.shared.b16 {%0,%1,%2,%3}, [%4];"
                 : "=r"(r[0]), "=r"(r[1]), "=r"(r[2]), "=r"(r[3]) : "r"(addr));
}
__device__ __forceinline__ void bulk_cp(uint32_t dst, const void* src, uint32_t bytes,
                                        uint32_t mbar) {
    asm volatile(
        "cp.async.bulk.shared::cluster.global.mbarrier::complete_tx::bytes "
        "[%0], [%1], %2, [%3];"
        :: "r"(dst), "l"(src), "r"(bytes), "r"(mbar) : "memory");
}
__device__ __forceinline__ int ld_acquire(const int* p) {
    int v;
    asm volatile("ld.acquire.gpu.global.b32 %0, [%1];" : "=r"(v) : "l"(p));
    return v;
}
#define MBARRIER_INIT(a, cnt) \
    asm volatile("mbarrier.init.shared.b64 [%0], %1;" \
                 :: "r"((uint32_t)(a)), "r"((uint32_t)(cnt)) : "memory")
#define MBARRIER_EXPECT_TX(a, bytes) \
    asm volatile("mbarrier.arrive.expect_tx.shared.b64 _, [%0], %1;" \
                 :: "r"((uint32_t)(a)), "r"((uint32_t)(bytes)) : "memory")
#define MBARRIER_WAIT_PARITY(a, par) do {                                        \
    uint32_t _m = (uint32_t)(a), _p = (uint32_t)(par), _d;                       \
    asm volatile("{\n\t.reg .pred p;\n\t"                                        \
        "mbarrier.try_wait.parity.acquire.cta.shared::cta.b64 p, [%1], %2;\n\t"  \
        "selp.b32 %0, 1, 0, p;\n\t}" : "=r"(_d) : "r"(_m), "r"(_p) : "memory");  \
    if (!_d) {                                                                   \
        asm volatile("{\n\t.reg .pred P1;\n\t"                                   \
            "WL_%=:\n\t"                                                         \
            "mbarrier.try_wait.parity.acquire.cta.shared::cta.b64 P1, [%0], %1, 0x989680;\n\t" \
            "@P1 bra.uni WD_%=;\n\tbra.uni WL_%=;\n\tWD_%=:\n\t}"                \
            :: "r"(_m), "r"(_p) : "memory");                                     \
    }                                                                            \
} while (0)

// ---------------------------------------------------------------------------
// Kernel 0: reset sync state (graph-replay safe)
// ---------------------------------------------------------------------------
__global__ void reset_kernel() {
    int i = threadIdx.x;
    if (i < 8) g_flag_q[i] = 0;
    for (int u = i; u < NBT; u += 256) g_flag_b[u] = 0;
    if (i == 0) g_conv_ctr = 0u;
}

// ---------------------------------------------------------------------------
// Kernel 1 (fused, persistent): prep (CTAs 0-127) -> convert queue (all) ->
// flag-gated persistent GEMM (all CTAs).
// ---------------------------------------------------------------------------
__global__ __launch_bounds__(512, 1) void fused_kernel(
    const int* __restrict__ x, const int* __restrict__ nb_idx,
    const float* __restrict__ lhs_w, const float* __restrict__ rel_w,
    const float* __restrict__ rhs_w,
    const float* __restrict__ W_w, const float* __restrict__ W_b,
    const float* __restrict__ W2_w, const float* __restrict__ W2_b,
    const float* __restrict__ Wo_w, const float* __restrict__ Wo_b,
    const float* __restrict__ Uo_w, const float* __restrict__ Uo_b,
    float* __restrict__ out, float* __restrict__ aux)
{
    extern __shared__ char dynsm[];
    float* sm = reinterpret_cast<float*>(dynsm);
    __shared__ unsigned cu;

    const int tid = threadIdx.x;
    const int lane = tid & 31;
    const int warp = tid >> 5;

    // ===================== Phase 1: prep (CTAs 0..127) =====================
    if (blockIdx.x < PREP_BLOCKS) {
        float* trp    = sm + P_TRP;
        float* w_sm   = sm + P_WSM;
        float* lr_sm  = sm + P_LR;
        float* w_part = sm + P_WPART;
        float* mden   = sm + P_MDEN;
        float* scb    = sm + P_SC;
        float* red    = sm + P_RED;
        float* g_sm   = sm + P_GSM;

        const int b0 = blockIdx.x * 8;
        const int grp = tid >> 8;
        const int t2 = tid & 255;

#pragma unroll
        for (int r = 0; r < 4; r++) {
            int bb = grp * 4 + r;
            int b = b0 + bb;
            int i0 = x[b * 3 + 0];
            int i1 = x[b * 3 + 1];
            int i2 = x[b * 3 + 2];
            float lv = lhs_w[(size_t)i0 * RANK + t2];
            float rv = rel_w[(size_t)i1 * RANK + t2];
            float hv = rhs_w[(size_t)i2 * RANK + t2];
            trp[bb * 512 + t2]       = lv;
            trp[bb * 512 + 256 + t2] = rv;
            lr_sm[bb * 256 + t2] = lv * rv;
            if (aux) {
                aux[(size_t)b * RANK + t2]              = lv;
                aux[262144 + (size_t)b * RANK + t2]     = rv;
                aux[2 * 262144 + (size_t)b * RANK + t2] = hv;
            }
        }
        __syncthreads();

        // w = trp_E @ W_w.T + W_b (direct rows, i-split across groups)
        {
            float acc[8];
#pragma unroll
            for (int bb = 0; bb < 8; bb++) acc[bb] = 0.f;
            const float* wrow = W_w + (size_t)t2 * 512 + grp * 256;
            for (int i = 0; i < 256; i += 4) {
                float4 wv = *reinterpret_cast<const float4*>(wrow + i);
#pragma unroll
                for (int bb = 0; bb < 8; bb++) {
                    const float4 tv = *reinterpret_cast<const float4*>(&trp[bb * 512 + grp * 256 + i]);
                    acc[bb] += wv.x * tv.x + wv.y * tv.y + wv.z * tv.z + wv.w * tv.w;
                }
            }
#pragma unroll
            for (int bb = 0; bb < 8; bb++) w_part[(grp * 8 + bb) * 256 + t2] = acc[bb];
        }
        __syncthreads();
        if (tid < 256) {
            float bias = W_b[t2];
#pragma unroll
            for (int bb = 0; bb < 8; bb++)
                w_sm[bb * 256 + t2] = w_part[bb * 256 + t2] + w_part[(8 + bb) * 256 + t2] + bias;
        }
        __syncthreads();

        // attention: 2 warps/row, 25 neighbors each, online softmax
        {
            const int bb = warp >> 1;
            const int h = warp & 1;
            const int b = b0 + bb;
            float wreg[8];
#pragma unroll
            for (int j = 0; j < 8; j++) wreg[j] = w_sm[bb * 256 + lane + 32 * j];
            float ctx_acc[8];
#pragma unroll
            for (int j = 0; j < 8; j++) ctx_acc[j] = 0.f;
            float Mx = -1e30f, den = 0.f;
            const int mbase = b * MAXNB + h * 25;
            for (int m = 0; m < 25; m++) {
                int nb = __ldg(&nb_idx[mbase + m]);
                const float* r = rhs_w + (size_t)nb * RANK;
                float rv[8];
                float s = 0.f;
#pragma unroll
                for (int j = 0; j < 8; j++) {
                    rv[j] = __ldg(&r[lane + 32 * j]);
                    s += wreg[j] * rv[j];
                }
#pragma unroll
                for (int o = 16; o > 0; o >>= 1) s += __shfl_xor_sync(0xffffffffu, s, o);
                float Mn = fmaxf(Mx, s);
                float scale = __expf(Mx - Mn);
                float p = __expf(s - Mn);
                den = den * scale + p;
#pragma unroll
                for (int j = 0; j < 8; j++) ctx_acc[j] = ctx_acc[j] * scale + p * rv[j];
                Mx = Mn;
            }
#pragma unroll
            for (int j = 0; j < 8; j++) trp[warp * 256 + lane + 32 * j] = ctx_acc[j];
            if (lane == 0) { mden[warp * 2 + 0] = Mx; mden[warp * 2 + 1] = den; }
        }
        __syncthreads();
        if (tid < 8) {
            float M0 = mden[(2 * tid) * 2 + 0],     d0 = mden[(2 * tid) * 2 + 1];
            float M1 = mden[(2 * tid + 1) * 2 + 0], d1 = mden[(2 * tid + 1) * 2 + 1];
            float M = fmaxf(M0, M1);
            float s0 = __expf(M0 - M), s1 = __expf(M1 - M);
            float inv = 1.f / (d0 * s0 + d1 * s1);
            scb[tid * 2 + 0] = s0 * inv;
            scb[tid * 2 + 1] = s1 * inv;
        }
        __syncthreads();
#pragma unroll
        for (int p = 0; p < 4; p++) {
            int idx = tid + p * 512;
            int bb = idx >> 8, t = idx & 255;
            w_part[bb * 256 + t] = trp[(2 * bb) * 256 + t] * scb[bb * 2 + 0]
                                 + trp[(2 * bb + 1) * 256 + t] * scb[bb * 2 + 1];
        }
        __syncthreads();

        // e_c matvec (direct rows, k-split across groups)
        {
            float acc[8];
#pragma unroll
            for (int bb = 0; bb < 8; bb++) acc[bb] = 0.f;
            const float* w2row = W2_w + (size_t)t2 * 256 + grp * 128;
            for (int k = 0; k < 128; k += 4) {
                float4 wv = *reinterpret_cast<const float4*>(w2row + k);
#pragma unroll
                for (int bb = 0; bb < 8; bb++) {
                    const float4 cv = *reinterpret_cast<const float4*>(&w_part[bb * 256 + grp * 128 + k]);
                    acc[bb] += wv.x * cv.x + wv.y * cv.y + wv.z * cv.z + wv.w * cv.w;
                }
            }
#pragma unroll
            for (int bb = 0; bb < 8; bb++) trp[(grp * 8 + bb) * 256 + t2] = acc[bb];
        }
        __syncthreads();

        float ec[8];
        if (tid < 256) {
            float bias = W2_b[t2];
#pragma unroll
            for (int bb = 0; bb < 8; bb++) {
                ec[bb] = trp[bb * 256 + t2] + trp[(8 + bb) * 256 + t2] + bias;
                if (aux) aux[3 * 262144 + (size_t)(b0 + bb) * RANK + t2] = ec[bb];
            }
            float uo = Uo_w[t2], wo = Wo_w[t2];
#pragma unroll
            for (int bb = 0; bb < 8; bb++) {
                float c = uo * lr_sm[bb * 256 + t2] + wo * ec[bb];
#pragma unroll
                for (int o = 16; o > 0; o >>= 1) c += __shfl_xor_sync(0xffffffffu, c, o);
                if (lane == 0) red[bb * 8 + warp] = c;
            }
        }
        __syncthreads();
        if (tid < 8) {
            float s = 0.f;
#pragma unroll
            for (int w = 0; w < 8; w++) s += red[tid * 8 + w];
            s += Uo_b[0] + Wo_b[0];
            g_sm[tid] = 1.f / (1.f + expf(-s));
        }
        __syncthreads();
        if (tid < 256) {
#pragma unroll
            for (int bb = 0; bb < 8; bb++) {
                float g = g_sm[bb];
                float q = lr_sm[bb * 256 + t2] * (g * ec[bb] + 1.f - g);
                g_q16[(size_t)(b0 + bb) * RANK + t2] = __float2half_rn(q * QSCALE);
            }
        }
        __threadfence();
        __syncthreads();
        if (tid == 0) atomicAdd(&g_flag_q[blockIdx.x >> 4], 1);
    }

    // ===================== Phase 2: convert queue (all CTAs) ================
    for (;;) {
        __syncthreads();
        if (tid == 0) cu = atomicAdd(&g_conv_ctr, 1u);
        __syncthreads();
        unsigned u = cu;
        if (u >= (unsigned)NBT) break;
        int r0 = (int)u * 256;
        int nrows = NENT - r0;
        if (nrows > 256) nrows = 256;
        for (int i = tid; i < nrows * 32; i += 512) {
            int row = i >> 5, c8 = (i & 31) * 8;
            size_t base = (size_t)(r0 + row) * RANK + c8;
            float4 v0 = *reinterpret_cast<const float4*>(rhs_w + base);
            float4 v1 = *reinterpret_cast<const float4*>(rhs_w + base + 4);
            __half2 h[4];
            h[0] = __floats2half2_rn(v0.x * RSCALE, v0.y * RSCALE);
            h[1] = __floats2half2_rn(v0.z * RSCALE, v0.w * RSCALE);
            h[2] = __floats2half2_rn(v1.x * RSCALE, v1.y * RSCALE);
            h[3] = __floats2half2_rn(v1.z * RSCALE, v1.w * RSCALE);
            *reinterpret_cast<uint4*>(g_rhs16 + base) = *reinterpret_cast<uint4*>(h);
        }
        __threadfence();
        __syncthreads();
        if (tid == 0) atomicExch(&g_flag_b[u], 1);
    }

    // ===================== Phase 3: persistent GEMM (all CTAs) ==============
    const int wm = warp & 1;     // m offset 64*wm
    const int wn = warp >> 1;    // n offset 32*wn  (0..7)
    const int gid = lane >> 2;
    const int qid = lane & 3;
    const int lrow = lane & 15;
    const int lcol16 = (lane >> 4) * 16;

    const uint32_t smem_u32 = (uint32_t)__cvta_generic_to_shared(dynsm);
    const uint32_t mbar0 = smem_u32;

    const int nct = gridDim.x;
    const int nloc = (NT - (int)blockIdx.x + nct - 1) / nct;
    if (nloc <= 0) return;
    const int Ltot = 2 * nloc;

    auto wait_tile = [&](int t) {   // tid 0 only
        int mt = t & 7, nt = t >> 3;
        while (ld_acquire(&g_flag_q[mt]) < 16) {}
        while (ld_acquire(&g_flag_b[nt]) == 0) {}
    };
    auto issue_chunk = [&](int L) {
        const int li = L >> 1, ch = L & 1;
        const int t = (int)blockIdx.x + li * nct;
        const int m0 = (t & 7) * BM;
        const int n0 = (t >> 3) * BN;
        const uint32_t sb = smem_u32 + SM_CTRL + (uint32_t)(ch * STG_BYTES);
        const uint32_t mb = mbar0 + ch * 8;
        if (tid < BM)
            bulk_cp(sb + (uint32_t)(tid * KP * 2),
                    g_q16 + (size_t)(m0 + tid) * RANK + ch * BKC, ROW_BYTES, mb);
        if (tid < BN) {
            int nr = n0 + tid;
            if (nr > NENT - 1) nr = NENT - 1;
            bulk_cp(sb + A_STG + (uint32_t)(tid * KP * 2),
                    g_rhs16 + (size_t)nr * RANK + ch * BKC, ROW_BYTES, mb);
        }
    };

    __syncthreads();
    if (tid == 0) {
        MBARRIER_INIT(mbar0 + 0, 1);
        MBARRIER_INIT(mbar0 + 8, 1);
    }
    __syncthreads();
    if (tid == 0) {
        wait_tile((int)blockIdx.x);
        MBARRIER_EXPECT_TX(mbar0 + 0, CHUNK_TX);
        if (Ltot > 1) MBARRIER_EXPECT_TX(mbar0 + 8, CHUNK_TX);
    }
    __syncthreads();
    issue_chunk(0);
    if (Ltot > 1) issue_chunk(1);

#pragma unroll 1
    for (int li = 0; li < nloc; li++) {
        const int t = (int)blockIdx.x + li * nct;
        const int m0 = (t & 7) * BM;
        const int n0 = (t >> 3) * BN;

        float acc[4][4][4];
#pragma unroll
        for (int i = 0; i < 4; i++)
#pragma unroll
            for (int f = 0; f < 4; f++)
#pragma unroll
                for (int r = 0; r < 4; r++) acc[i][f][r] = 0.f;

#pragma unroll 1
        for (int ch = 0; ch < 2; ch++) {
            const int L = li * 2 + ch;
            MBARRIER_WAIT_PARITY(mbar0 + ch * 8, li & 1);

            const uint32_t abase = smem_u32 + SM_CTRL + (uint32_t)(ch * STG_BYTES);
            const uint32_t bbase = abase + A_STG;
#pragma unroll
            for (int kk = 0; kk < BKC / 16; kk++) {
                uint32_t a[4][4];
#pragma unroll
                for (int i = 0; i < 4; i++)
                    ldsm_x4(a[i], abase + (uint32_t)((wm * 64 + i * 16 + lrow) * (KP * 2)
                                                     + kk * 32 + lcol16));
                uint32_t b[2][4];
#pragma unroll
                for (int j = 0; j < 2; j++)
                    ldsm_x4(b[j], bbase + (uint32_t)((wn * 32 + j * 16 + lrow) * (KP * 2)
                                                     + kk * 32 + lcol16));
#pragma unroll
                for (int i = 0; i < 4; i++)
#pragma unroll
                    for (int f = 0; f < 4; f++) {
                        int j = f >> 1, h = f & 1;
                        mma_f16(acc[i][f], a[i], b[j][h], b[j][h + 2]);
                    }
            }

            if (L + 2 < Ltot) {
                __syncthreads();
                if (tid == 0) {
                    if (ch == 0) wait_tile((int)blockIdx.x + (li + 1) * nct);
                    MBARRIER_EXPECT_TX(mbar0 + ch * 8, CHUNK_TX);
                }
                __syncthreads();
                issue_chunk(L + 2);
            }
        }

        // epilogue: descale + streaming stores
#pragma unroll
        for (int i = 0; i < 4; i++) {
            int r = m0 + wm * 64 + i * 16 + gid;
#pragma unroll
            for (int f = 0; f < 4; f++) {
                int cb = n0 + wn * 32 + f * 8 + 2 * qid;
                if (cb < NENT) {
                    __stcs(reinterpret_cast<float2*>(out + (size_t)r * NENT + cb),
                           make_float2(acc[i][f][0] * OSCALE, acc[i][f][1] * OSCALE));
                    __stcs(reinterpret_cast<float2*>(out + (size_t)(r + 8) * NENT + cb),
                           make_float2(acc[i][f][2] * OSCALE, acc[i][f][3] * OSCALE));
                }
            }
        }
    }
}

// ---------------------------------------------------------------------------
extern "C" void kernel_launch(void* const* d_in, const int* in_sizes, int n_in,
                              void* d_out, int out_size) {
    const int*   x      = (const int*)d_in[0];
    const int*   nb     = (const int*)d_in[1];
    const float* lhs_w  = (const float*)d_in[2];
    const float* rel_w  = (const float*)d_in[3];
    const float* rhs_w  = (const float*)d_in[4];
    const float* W_w    = (const float*)d_in[5];
    const float* W_b    = (const float*)d_in[6];
    const float* W2_w   = (const float*)d_in[7];
    const float* W2_b   = (const float*)d_in[8];
    const float* Wo_w   = (const float*)d_in[9];
    const float* Wo_b   = (const float*)d_in[10];
    const float* Uo_w   = (const float*)d_in[11];
    const float* Uo_b   = (const float*)d_in[12];
    float* out = (float*)d_out;

    float* aux = nullptr;
    if (out_size >= 102400000 + 4 * 262144) aux = out + 102400000;

    static int nsm = 0;
    if (!nsm) {
        cudaFuncSetAttribute(fused_kernel,
                             cudaFuncAttributeMaxDynamicSharedMemorySize, SMEM_BYTES);
        int dev = 0;
        cudaGetDevice(&dev);
        cudaDeviceGetAttribute(&nsm, cudaDevAttrMultiProcessorCount, dev);
        if (nsm <= 0) nsm = 148;
        if (nsm > 1024) nsm = 1024;
    }

    reset_kernel<<<1, 256>>>();
    fused_kernel<<<nsm, 512, SMEM_BYTES>>>(x, nb, lhs_w, rel_w, rhs_w,
                                           W_w, W_b, W2_w, W2_b,
                                           Wo_w, Wo_b, Uo_w, Uo_b, out, aux);
}